// round 8
// baseline (speedup 1.0000x reference)
#include <cuda_runtime.h>
#include <math.h>

#define F_ 4
#define E_ 8
#define B_ 4096
#define D_ 512
#define H_ 1024
#define O_ 512
#define FE_ (F_*E_)

typedef unsigned long long ull;

// Scratch (no cudaMalloc allowed): gate (pre-scaled by 1/F) and gated hidden activations.
__device__ __align__(16) float g_gate[F_ * B_ * E_];                 // 512 KB
__device__ __align__(16) float g_hidden[(size_t)FE_ * B_ * H_];      // 512 MB

// ---- packed fp32x2 helpers (Blackwell FFMA2: 2x fp32 FMA throughput) ----
__device__ __forceinline__ ull ffma2(ull a, ull b, ull c) {
    ull d;
    asm("fma.rn.f32x2 %0, %1, %2, %3;" : "=l"(d) : "l"(a), "l"(b), "l"(c));
    return d;
}
__device__ __forceinline__ ull pack2(float x) {
    ull r;
    asm("mov.b64 %0, {%1, %2};" : "=l"(r) : "f"(x), "f"(x));
    return r;
}
__device__ __forceinline__ float2 unpack2(ull v) {
    float2 r;
    asm("mov.b64 {%0, %1}, %2;" : "=f"(r.x), "=f"(r.y) : "l"(v));
    return r;
}

// ============================================================================
// Kernel 1: gate logits + softmax, pre-scaled by 1/F. One thread per (f, b).
// ============================================================================
__global__ void gate_kernel(const float* __restrict__ feat,
                            const float* __restrict__ Wg,
                            const float* __restrict__ bg)
{
    const int b = blockIdx.x * blockDim.x + threadIdx.x;
    const int f = blockIdx.y;
    const float* x  = feat + ((size_t)f * B_ + b) * D_;
    const float* wg = Wg + (size_t)f * D_ * E_;

    float acc[E_];
#pragma unroll
    for (int e = 0; e < E_; ++e) acc[e] = bg[f * E_ + e];

    for (int d0 = 0; d0 < D_; d0 += 4) {
        float4 xv = *(const float4*)(x + d0);
        float xa[4] = {xv.x, xv.y, xv.z, xv.w};
#pragma unroll
        for (int q = 0; q < 4; ++q) {
            const float4* w = (const float4*)(wg + (size_t)(d0 + q) * E_);
            float4 w0 = w[0], w1 = w[1];
            acc[0] = fmaf(xa[q], w0.x, acc[0]);
            acc[1] = fmaf(xa[q], w0.y, acc[1]);
            acc[2] = fmaf(xa[q], w0.z, acc[2]);
            acc[3] = fmaf(xa[q], w0.w, acc[3]);
            acc[4] = fmaf(xa[q], w1.x, acc[4]);
            acc[5] = fmaf(xa[q], w1.y, acc[5]);
            acc[6] = fmaf(xa[q], w1.z, acc[6]);
            acc[7] = fmaf(xa[q], w1.w, acc[7]);
        }
    }
    float mx = acc[0];
#pragma unroll
    for (int e = 1; e < E_; ++e) mx = fmaxf(mx, acc[e]);
    float s = 0.f;
#pragma unroll
    for (int e = 0; e < E_; ++e) { acc[e] = expf(acc[e] - mx); s += acc[e]; }
    const float inv = 1.f / (s * (float)F_);   // fold mean-over-F here
#pragma unroll
    for (int e = 0; e < E_; ++e)
        g_gate[((size_t)f * B_ + b) * E_ + e] = acc[e] * inv;
}

// ============================================================================
// Kernel 2: hidden = gate * relu(X @ W1 + b1), per (f,e) batch.
// 128x128 tile, BK=16, 256 threads, 8x8/thread, FFMA2, double-buffered smem.
// ============================================================================
__global__ __launch_bounds__(256, 2)
void hidden_kernel(const float* __restrict__ feat,
                   const float* __restrict__ W1,
                   const float* __restrict__ b1)
{
    const int fe = blockIdx.z;
    const int f = fe >> 3, e = fe & 7;
    const int m0 = blockIdx.y * 128;
    const int n0 = blockIdx.x * 128;

    const float* __restrict__ A  = feat + (size_t)f * (B_ * D_);           // [B,D]
    const float* __restrict__ Bg = W1 + (size_t)fe * (D_ * H_);            // [D,H]
    float* __restrict__ C = g_hidden + (size_t)fe * ((size_t)B_ * H_);     // [B,H]

    __shared__ float As[2][16][132];   // transposed: As[k][m], +4 pad
    __shared__ float Bs[2][16][128];   // Bs[k][n]

    const int tid = threadIdx.x;
    const int tx = tid & 15;   // n-thread (split cols: tx*4 and 64+tx*4)
    const int ty = tid >> 4;   // m-thread (split rows: ty*4 and 64+ty*4)

    const int a_row = tid >> 2;            // 0..63 (and +64)
    const int a_c4  = (tid & 3) << 2;      // k offset within tile
    const int b_row = tid >> 5;            // 0..7 (and +8)
    const int b_c4  = (tid & 31) << 2;     // n offset

    ull acc[8][4];
#pragma unroll
    for (int i = 0; i < 8; ++i)
#pragma unroll
        for (int j = 0; j < 4; ++j) acc[i][j] = 0ull;

    float4 ar0, ar1, br0, br1;

    auto ldg_tile = [&](int k0) {
        const float* pa = A + (size_t)(m0 + a_row) * D_ + k0 + a_c4;
        ar0 = *(const float4*)pa;
        ar1 = *(const float4*)(pa + (size_t)64 * D_);
        const float* pb = Bg + (size_t)(k0 + b_row) * H_ + n0 + b_c4;
        br0 = *(const float4*)pb;
        br1 = *(const float4*)(pb + (size_t)8 * H_);
    };
    auto sts_tile = [&](int buf) {
        As[buf][a_c4 + 0][a_row] = ar0.x;
        As[buf][a_c4 + 1][a_row] = ar0.y;
        As[buf][a_c4 + 2][a_row] = ar0.z;
        As[buf][a_c4 + 3][a_row] = ar0.w;
        As[buf][a_c4 + 0][a_row + 64] = ar1.x;
        As[buf][a_c4 + 1][a_row + 64] = ar1.y;
        As[buf][a_c4 + 2][a_row + 64] = ar1.z;
        As[buf][a_c4 + 3][a_row + 64] = ar1.w;
        *(float4*)&Bs[buf][b_row][b_c4] = br0;
        *(float4*)&Bs[buf][b_row + 8][b_c4] = br1;
    };

    ldg_tile(0);
    sts_tile(0);

    const int KT = D_ / 16;  // 32
    for (int t = 0; t < KT; ++t) {
        __syncthreads();
        if (t + 1 < KT) ldg_tile((t + 1) * 16);
        const int cur = t & 1;
#pragma unroll
        for (int k = 0; k < 16; ++k) {
            float4 a0 = *(const float4*)&As[cur][k][ty * 4];
            float4 a1 = *(const float4*)&As[cur][k][64 + ty * 4];
            ulonglong2 bb0 = *(const ulonglong2*)&Bs[cur][k][tx * 4];
            ulonglong2 bb1 = *(const ulonglong2*)&Bs[cur][k][64 + tx * 4];
            float af[8] = {a0.x, a0.y, a0.z, a0.w, a1.x, a1.y, a1.z, a1.w};
            ull bv[4] = {bb0.x, bb0.y, bb1.x, bb1.y};
#pragma unroll
            for (int mi = 0; mi < 8; ++mi) {
                ull am = pack2(af[mi]);
#pragma unroll
                for (int j = 0; j < 4; ++j)
                    acc[mi][j] = ffma2(am, bv[j], acc[mi][j]);
            }
        }
        if (t + 1 < KT) sts_tile((t + 1) & 1);
    }

    // Epilogue: + b1, relu, * gate(1/F-scaled), store to g_hidden
    float4 b1a = *(const float4*)(b1 + (size_t)fe * H_ + n0 + tx * 4);
    float4 b1b = *(const float4*)(b1 + (size_t)fe * H_ + n0 + 64 + tx * 4);
    float b1v[8] = {b1a.x, b1a.y, b1a.z, b1a.w, b1b.x, b1b.y, b1b.z, b1b.w};

#pragma unroll
    for (int mi = 0; mi < 8; ++mi) {
        const int m = m0 + ((mi < 4) ? (ty * 4 + mi) : (64 + ty * 4 + mi - 4));
        const float g = g_gate[((size_t)f * B_ + m) * E_ + e];
        float v[8];
#pragma unroll
        for (int j = 0; j < 4; ++j) {
            float2 p = unpack2(acc[mi][j]);
            v[2 * j] = p.x; v[2 * j + 1] = p.y;
        }
        float4 o0, o1;
        o0.x = fmaxf(v[0] + b1v[0], 0.f) * g;
        o0.y = fmaxf(v[1] + b1v[1], 0.f) * g;
        o0.z = fmaxf(v[2] + b1v[2], 0.f) * g;
        o0.w = fmaxf(v[3] + b1v[3], 0.f) * g;
        o1.x = fmaxf(v[4] + b1v[4], 0.f) * g;
        o1.y = fmaxf(v[5] + b1v[5], 0.f) * g;
        o1.z = fmaxf(v[6] + b1v[6], 0.f) * g;
        o1.w = fmaxf(v[7] + b1v[7], 0.f) * g;
        *(float4*)&C[(size_t)m * H_ + n0 + tx * 4] = o0;
        *(float4*)&C[(size_t)m * H_ + n0 + 64 + tx * 4] = o1;
    }
}

// ============================================================================
// Kernel 3: out[b,o] = sum_{fe,k} h'[fe,b,k]*W2[fe,k,o] + sum_fe gate*b2.
// One GEMM with K = 32*1024 = 32768. 128x64 tile, 128 threads, 8x8/thread.
// ============================================================================
__global__ __launch_bounds__(128, 2)
void out_kernel(const float* __restrict__ W2,
                const float* __restrict__ b2,
                float* __restrict__ out)
{
    const int m0 = blockIdx.y * 128;
    const int n0 = blockIdx.x * 64;

    __shared__ float As[2][16][132];
    __shared__ float Bs[2][16][64];

    const int tid = threadIdx.x;
    const int tx = tid & 7;    // n: cols tx*4 and 32+tx*4
    const int ty = tid >> 3;   // m: rows ty*4 and 64+ty*4

    const int a_row = tid >> 2;          // 0..31 (+32*j)
    const int a_c4  = (tid & 3) << 2;
    const int b_row = tid >> 4;          // 0..7 (+8)
    const int b_c4  = (tid & 15) << 2;   // 0..60

    ull acc[8][4];
#pragma unroll
    for (int i = 0; i < 8; ++i)
#pragma unroll
        for (int j = 0; j < 4; ++j) acc[i][j] = 0ull;

    float4 ar[4], br0, br1;

    auto ldg_tile = [&](int t) {
        const int fe = t >> 6;            // H_/16 = 64 k-tiles per fe
        const int k0 = (t & 63) << 4;
        const float* pa = g_hidden + ((size_t)fe * B_ + m0 + a_row) * H_ + k0 + a_c4;
#pragma unroll
        for (int j = 0; j < 4; ++j)
            ar[j] = *(const float4*)(pa + (size_t)(32 * j) * H_);
        const float* pb = W2 + ((size_t)fe * H_ + k0 + b_row) * O_ + n0 + b_c4;
        br0 = *(const float4*)pb;
        br1 = *(const float4*)(pb + (size_t)8 * O_);
    };
    auto sts_tile = [&](int buf) {
#pragma unroll
        for (int j = 0; j < 4; ++j) {
            As[buf][a_c4 + 0][a_row + 32 * j] = ar[j].x;
            As[buf][a_c4 + 1][a_row + 32 * j] = ar[j].y;
            As[buf][a_c4 + 2][a_row + 32 * j] = ar[j].z;
            As[buf][a_c4 + 3][a_row + 32 * j] = ar[j].w;
        }
        *(float4*)&Bs[buf][b_row][b_c4] = br0;
        *(float4*)&Bs[buf][b_row + 8][b_c4] = br1;
    };

    ldg_tile(0);
    sts_tile(0);

    const int NT = FE_ * (H_ / 16);   // 2048
    for (int t = 0; t < NT; ++t) {
        __syncthreads();
        if (t + 1 < NT) ldg_tile(t + 1);
        const int cur = t & 1;
#pragma unroll
        for (int k = 0; k < 16; ++k) {
            float4 a0 = *(const float4*)&As[cur][k][ty * 4];
            float4 a1 = *(const float4*)&As[cur][k][64 + ty * 4];
            ulonglong2 bb0 = *(const ulonglong2*)&Bs[cur][k][tx * 4];
            ulonglong2 bb1 = *(const ulonglong2*)&Bs[cur][k][32 + tx * 4];
            float af[8] = {a0.x, a0.y, a0.z, a0.w, a1.x, a1.y, a1.z, a1.w};
            ull bv[4] = {bb0.x, bb0.y, bb1.x, bb1.y};
#pragma unroll
            for (int mi = 0; mi < 8; ++mi) {
                ull am = pack2(af[mi]);
#pragma unroll
                for (int j = 0; j < 4; ++j)
                    acc[mi][j] = ffma2(am, bv[j], acc[mi][j]);
            }
        }
        if (t + 1 < NT) sts_tile((t + 1) & 1);
    }

    // Epilogue: add sum_fe gate(f,m,e)/F * b2(fe,o) and store.
    const int c0 = n0 + tx * 4;
    const int c1 = n0 + 32 + tx * 4;
#pragma unroll
    for (int mi = 0; mi < 8; ++mi) {
        const int m = m0 + ((mi < 4) ? (ty * 4 + mi) : (64 + ty * 4 + mi - 4));
        float v[8];
#pragma unroll
        for (int j = 0; j < 4; ++j) {
            float2 p = unpack2(acc[mi][j]);
            v[2 * j] = p.x; v[2 * j + 1] = p.y;
        }
        float bias[8] = {0.f, 0.f, 0.f, 0.f, 0.f, 0.f, 0.f, 0.f};
#pragma unroll 4
        for (int fe = 0; fe < FE_; ++fe) {
            const float g = g_gate[((size_t)(fe >> 3) * B_ + m) * E_ + (fe & 7)];
            const float4 bb0 = *(const float4*)(b2 + (size_t)fe * O_ + c0);
            const float4 bb1 = *(const float4*)(b2 + (size_t)fe * O_ + c1);
            bias[0] = fmaf(g, bb0.x, bias[0]);
            bias[1] = fmaf(g, bb0.y, bias[1]);
            bias[2] = fmaf(g, bb0.z, bias[2]);
            bias[3] = fmaf(g, bb0.w, bias[3]);
            bias[4] = fmaf(g, bb1.x, bias[4]);
            bias[5] = fmaf(g, bb1.y, bias[5]);
            bias[6] = fmaf(g, bb1.z, bias[6]);
            bias[7] = fmaf(g, bb1.w, bias[7]);
        }
        float4 o0 = {v[0] + bias[0], v[1] + bias[1], v[2] + bias[2], v[3] + bias[3]};
        float4 o1 = {v[4] + bias[4], v[5] + bias[5], v[6] + bias[6], v[7] + bias[7]};
        *(float4*)&out[(size_t)m * O_ + c0] = o0;
        *(float4*)&out[(size_t)m * O_ + c1] = o1;
    }
}

// ============================================================================
extern "C" void kernel_launch(void* const* d_in, const int* in_sizes, int n_in,
                              void* d_out, int out_size)
{
    const float* feat = (const float*)d_in[0];   // [F,B,D]
    const float* W1   = (const float*)d_in[1];   // [F,E,D,H]
    const float* b1   = (const float*)d_in[2];   // [F,E,H]
    const float* W2   = (const float*)d_in[3];   // [F,E,H,O]
    const float* b2   = (const float*)d_in[4];   // [F,E,O]
    const float* Wg   = (const float*)d_in[5];   // [F,D,E]
    const float* bg   = (const float*)d_in[6];   // [F,E]
    float* out = (float*)d_out;                  // [B,O]

    gate_kernel<<<dim3(B_ / 256, F_), 256>>>(feat, Wg, bg);
    hidden_kernel<<<dim3(H_ / 128, B_ / 128, FE_), 256>>>(feat, W1, b1);
    out_kernel<<<dim3(O_ / 64, B_ / 128), 128>>>(W2, b2, out);
}

// round 9
// speedup vs baseline: 1.0004x; 1.0004x over previous
#include <cuda_runtime.h>
#include <math.h>

#define F_ 4
#define E_ 8
#define B_ 4096
#define D_ 512
#define H_ 1024
#define O_ 512
#define FE_ (F_*E_)

typedef unsigned long long ull;

// Scratch (no cudaMalloc allowed): gate (pre-scaled by 1/F) and gated hidden activations.
__device__ __align__(16) float g_gate[F_ * B_ * E_];                 // 512 KB
__device__ __align__(16) float g_hidden[(size_t)FE_ * B_ * H_];      // 512 MB

// ---- packed fp32x2 helpers (Blackwell FFMA2: 2x fp32 FMA throughput) ----
__device__ __forceinline__ ull ffma2(ull a, ull b, ull c) {
    ull d;
    asm("fma.rn.f32x2 %0, %1, %2, %3;" : "=l"(d) : "l"(a), "l"(b), "l"(c));
    return d;
}
__device__ __forceinline__ ull pack2(float x) {
    ull r;
    asm("mov.b64 %0, {%1, %2};" : "=l"(r) : "f"(x), "f"(x));
    return r;
}
__device__ __forceinline__ float2 unpack2(ull v) {
    float2 r;
    asm("mov.b64 {%0, %1}, %2;" : "=f"(r.x), "=f"(r.y) : "l"(v));
    return r;
}

// ============================================================================
// Kernel 1: gate logits + softmax, pre-scaled by 1/F. One thread per (f, b).
// ============================================================================
__global__ void gate_kernel(const float* __restrict__ feat,
                            const float* __restrict__ Wg,
                            const float* __restrict__ bg)
{
    const int b = blockIdx.x * blockDim.x + threadIdx.x;
    const int f = blockIdx.y;
    const float* x  = feat + ((size_t)f * B_ + b) * D_;
    const float* wg = Wg + (size_t)f * D_ * E_;

    float acc[E_];
#pragma unroll
    for (int e = 0; e < E_; ++e) acc[e] = bg[f * E_ + e];

    for (int d0 = 0; d0 < D_; d0 += 4) {
        float4 xv = *(const float4*)(x + d0);
        float xa[4] = {xv.x, xv.y, xv.z, xv.w};
#pragma unroll
        for (int q = 0; q < 4; ++q) {
            const float4* w = (const float4*)(wg + (size_t)(d0 + q) * E_);
            float4 w0 = w[0], w1 = w[1];
            acc[0] = fmaf(xa[q], w0.x, acc[0]);
            acc[1] = fmaf(xa[q], w0.y, acc[1]);
            acc[2] = fmaf(xa[q], w0.z, acc[2]);
            acc[3] = fmaf(xa[q], w0.w, acc[3]);
            acc[4] = fmaf(xa[q], w1.x, acc[4]);
            acc[5] = fmaf(xa[q], w1.y, acc[5]);
            acc[6] = fmaf(xa[q], w1.z, acc[6]);
            acc[7] = fmaf(xa[q], w1.w, acc[7]);
        }
    }
    float mx = acc[0];
#pragma unroll
    for (int e = 1; e < E_; ++e) mx = fmaxf(mx, acc[e]);
    float s = 0.f;
#pragma unroll
    for (int e = 0; e < E_; ++e) { acc[e] = expf(acc[e] - mx); s += acc[e]; }
    const float inv = 1.f / (s * (float)F_);   // fold mean-over-F here
#pragma unroll
    for (int e = 0; e < E_; ++e)
        g_gate[((size_t)f * B_ + b) * E_ + e] = acc[e] * inv;
}

// ============================================================================
// Kernel 2: hidden = gate * relu(X @ W1 + b1), per (f,e) batch.
// 128x128 tile, BK=16, 256 threads, 8x8/thread, FFMA2, double-buffered smem.
// ============================================================================
__global__ __launch_bounds__(256, 2)
void hidden_kernel(const float* __restrict__ feat,
                   const float* __restrict__ W1,
                   const float* __restrict__ b1)
{
    const int fe = blockIdx.z;
    const int f = fe >> 3, e = fe & 7;
    const int m0 = blockIdx.y * 128;
    const int n0 = blockIdx.x * 128;

    const float* __restrict__ A  = feat + (size_t)f * (B_ * D_);           // [B,D]
    const float* __restrict__ Bg = W1 + (size_t)fe * (D_ * H_);            // [D,H]
    float* __restrict__ C = g_hidden + (size_t)fe * ((size_t)B_ * H_);     // [B,H]

    __shared__ float As[2][16][132];   // transposed: As[k][m], +4 pad
    __shared__ float Bs[2][16][128];   // Bs[k][n]

    const int tid = threadIdx.x;
    const int tx = tid & 15;   // n-thread (split cols: tx*4 and 64+tx*4)
    const int ty = tid >> 4;   // m-thread (split rows: ty*4 and 64+ty*4)

    const int a_row = tid >> 2;            // 0..63 (and +64)
    const int a_c4  = (tid & 3) << 2;      // k offset within tile
    const int b_row = tid >> 5;            // 0..7 (and +8)
    const int b_c4  = (tid & 31) << 2;     // n offset

    ull acc[8][4];
#pragma unroll
    for (int i = 0; i < 8; ++i)
#pragma unroll
        for (int j = 0; j < 4; ++j) acc[i][j] = 0ull;

    float4 ar0, ar1, br0, br1;

    auto ldg_tile = [&](int k0) {
        const float* pa = A + (size_t)(m0 + a_row) * D_ + k0 + a_c4;
        ar0 = *(const float4*)pa;
        ar1 = *(const float4*)(pa + (size_t)64 * D_);
        const float* pb = Bg + (size_t)(k0 + b_row) * H_ + n0 + b_c4;
        br0 = *(const float4*)pb;
        br1 = *(const float4*)(pb + (size_t)8 * H_);
    };
    auto sts_tile = [&](int buf) {
        As[buf][a_c4 + 0][a_row] = ar0.x;
        As[buf][a_c4 + 1][a_row] = ar0.y;
        As[buf][a_c4 + 2][a_row] = ar0.z;
        As[buf][a_c4 + 3][a_row] = ar0.w;
        As[buf][a_c4 + 0][a_row + 64] = ar1.x;
        As[buf][a_c4 + 1][a_row + 64] = ar1.y;
        As[buf][a_c4 + 2][a_row + 64] = ar1.z;
        As[buf][a_c4 + 3][a_row + 64] = ar1.w;
        *(float4*)&Bs[buf][b_row][b_c4] = br0;
        *(float4*)&Bs[buf][b_row + 8][b_c4] = br1;
    };

    ldg_tile(0);
    sts_tile(0);

    const int KT = D_ / 16;  // 32
    for (int t = 0; t < KT; ++t) {
        __syncthreads();
        if (t + 1 < KT) ldg_tile((t + 1) * 16);
        const int cur = t & 1;
#pragma unroll
        for (int k = 0; k < 16; ++k) {
            float4 a0 = *(const float4*)&As[cur][k][ty * 4];
            float4 a1 = *(const float4*)&As[cur][k][64 + ty * 4];
            ulonglong2 bb0 = *(const ulonglong2*)&Bs[cur][k][tx * 4];
            ulonglong2 bb1 = *(const ulonglong2*)&Bs[cur][k][64 + tx * 4];
            float af[8] = {a0.x, a0.y, a0.z, a0.w, a1.x, a1.y, a1.z, a1.w};
            ull bv[4] = {bb0.x, bb0.y, bb1.x, bb1.y};
#pragma unroll
            for (int mi = 0; mi < 8; ++mi) {
                ull am = pack2(af[mi]);
#pragma unroll
                for (int j = 0; j < 4; ++j)
                    acc[mi][j] = ffma2(am, bv[j], acc[mi][j]);
            }
        }
        if (t + 1 < KT) sts_tile((t + 1) & 1);
    }

    // Epilogue: + b1, relu, * gate(1/F-scaled), store to g_hidden
    float4 b1a = *(const float4*)(b1 + (size_t)fe * H_ + n0 + tx * 4);
    float4 b1b = *(const float4*)(b1 + (size_t)fe * H_ + n0 + 64 + tx * 4);
    float b1v[8] = {b1a.x, b1a.y, b1a.z, b1a.w, b1b.x, b1b.y, b1b.z, b1b.w};

#pragma unroll
    for (int mi = 0; mi < 8; ++mi) {
        const int m = m0 + ((mi < 4) ? (ty * 4 + mi) : (64 + ty * 4 + mi - 4));
        const float g = g_gate[((size_t)f * B_ + m) * E_ + e];
        float v[8];
#pragma unroll
        for (int j = 0; j < 4; ++j) {
            float2 p = unpack2(acc[mi][j]);
            v[2 * j] = p.x; v[2 * j + 1] = p.y;
        }
        float4 o0, o1;
        o0.x = fmaxf(v[0] + b1v[0], 0.f) * g;
        o0.y = fmaxf(v[1] + b1v[1], 0.f) * g;
        o0.z = fmaxf(v[2] + b1v[2], 0.f) * g;
        o0.w = fmaxf(v[3] + b1v[3], 0.f) * g;
        o1.x = fmaxf(v[4] + b1v[4], 0.f) * g;
        o1.y = fmaxf(v[5] + b1v[5], 0.f) * g;
        o1.z = fmaxf(v[6] + b1v[6], 0.f) * g;
        o1.w = fmaxf(v[7] + b1v[7], 0.f) * g;
        *(float4*)&C[(size_t)m * H_ + n0 + tx * 4] = o0;
        *(float4*)&C[(size_t)m * H_ + n0 + 64 + tx * 4] = o1;
    }
}

// ============================================================================
// Kernel 3: out[b,o] = sum_{fe,k} h'[fe,b,k]*W2[fe,k,o] + sum_fe gate*b2.
// One GEMM with K = 32*1024 = 32768. 128x64 tile, 128 threads, 8x8/thread.
// ============================================================================
__global__ __launch_bounds__(128, 2)
void out_kernel(const float* __restrict__ W2,
                const float* __restrict__ b2,
                float* __restrict__ out)
{
    const int m0 = blockIdx.y * 128;
    const int n0 = blockIdx.x * 64;

    __shared__ float As[2][16][132];
    __shared__ float Bs[2][16][64];

    const int tid = threadIdx.x;
    const int tx = tid & 7;    // n: cols tx*4 and 32+tx*4
    const int ty = tid >> 3;   // m: rows ty*4 and 64+ty*4

    const int a_row = tid >> 2;          // 0..31 (+32*j)
    const int a_c4  = (tid & 3) << 2;
    const int b_row = tid >> 4;          // 0..7 (+8)
    const int b_c4  = (tid & 15) << 2;   // 0..60

    ull acc[8][4];
#pragma unroll
    for (int i = 0; i < 8; ++i)
#pragma unroll
        for (int j = 0; j < 4; ++j) acc[i][j] = 0ull;

    float4 ar[4], br0, br1;

    auto ldg_tile = [&](int t) {
        const int fe = t >> 6;            // H_/16 = 64 k-tiles per fe
        const int k0 = (t & 63) << 4;
        const float* pa = g_hidden + ((size_t)fe * B_ + m0 + a_row) * H_ + k0 + a_c4;
#pragma unroll
        for (int j = 0; j < 4; ++j)
            ar[j] = *(const float4*)(pa + (size_t)(32 * j) * H_);
        const float* pb = W2 + ((size_t)fe * H_ + k0 + b_row) * O_ + n0 + b_c4;
        br0 = *(const float4*)pb;
        br1 = *(const float4*)(pb + (size_t)8 * O_);
    };
    auto sts_tile = [&](int buf) {
#pragma unroll
        for (int j = 0; j < 4; ++j) {
            As[buf][a_c4 + 0][a_row + 32 * j] = ar[j].x;
            As[buf][a_c4 + 1][a_row + 32 * j] = ar[j].y;
            As[buf][a_c4 + 2][a_row + 32 * j] = ar[j].z;
            As[buf][a_c4 + 3][a_row + 32 * j] = ar[j].w;
        }
        *(float4*)&Bs[buf][b_row][b_c4] = br0;
        *(float4*)&Bs[buf][b_row + 8][b_c4] = br1;
    };

    ldg_tile(0);
    sts_tile(0);

    const int NT = FE_ * (H_ / 16);   // 2048
    for (int t = 0; t < NT; ++t) {
        __syncthreads();
        if (t + 1 < NT) ldg_tile(t + 1);
        const int cur = t & 1;
#pragma unroll
        for (int k = 0; k < 16; ++k) {
            float4 a0 = *(const float4*)&As[cur][k][ty * 4];
            float4 a1 = *(const float4*)&As[cur][k][64 + ty * 4];
            ulonglong2 bb0 = *(const ulonglong2*)&Bs[cur][k][tx * 4];
            ulonglong2 bb1 = *(const ulonglong2*)&Bs[cur][k][32 + tx * 4];
            float af[8] = {a0.x, a0.y, a0.z, a0.w, a1.x, a1.y, a1.z, a1.w};
            ull bv[4] = {bb0.x, bb0.y, bb1.x, bb1.y};
#pragma unroll
            for (int mi = 0; mi < 8; ++mi) {
                ull am = pack2(af[mi]);
#pragma unroll
                for (int j = 0; j < 4; ++j)
                    acc[mi][j] = ffma2(am, bv[j], acc[mi][j]);
            }
        }
        if (t + 1 < NT) sts_tile((t + 1) & 1);
    }

    // Epilogue: add sum_fe gate(f,m,e)/F * b2(fe,o) and store.
    const int c0 = n0 + tx * 4;
    const int c1 = n0 + 32 + tx * 4;
#pragma unroll
    for (int mi = 0; mi < 8; ++mi) {
        const int m = m0 + ((mi < 4) ? (ty * 4 + mi) : (64 + ty * 4 + mi - 4));
        float v[8];
#pragma unroll
        for (int j = 0; j < 4; ++j) {
            float2 p = unpack2(acc[mi][j]);
            v[2 * j] = p.x; v[2 * j + 1] = p.y;
        }
        float bias[8] = {0.f, 0.f, 0.f, 0.f, 0.f, 0.f, 0.f, 0.f};
#pragma unroll 4
        for (int fe = 0; fe < FE_; ++fe) {
            const float g = g_gate[((size_t)(fe >> 3) * B_ + m) * E_ + (fe & 7)];
            const float4 bb0 = *(const float4*)(b2 + (size_t)fe * O_ + c0);
            const float4 bb1 = *(const float4*)(b2 + (size_t)fe * O_ + c1);
            bias[0] = fmaf(g, bb0.x, bias[0]);
            bias[1] = fmaf(g, bb0.y, bias[1]);
            bias[2] = fmaf(g, bb0.z, bias[2]);
            bias[3] = fmaf(g, bb0.w, bias[3]);
            bias[4] = fmaf(g, bb1.x, bias[4]);
            bias[5] = fmaf(g, bb1.y, bias[5]);
            bias[6] = fmaf(g, bb1.z, bias[6]);
            bias[7] = fmaf(g, bb1.w, bias[7]);
        }
        float4 o0 = {v[0] + bias[0], v[1] + bias[1], v[2] + bias[2], v[3] + bias[3]};
        float4 o1 = {v[4] + bias[4], v[5] + bias[5], v[6] + bias[6], v[7] + bias[7]};
        *(float4*)&out[(size_t)m * O_ + c0] = o0;
        *(float4*)&out[(size_t)m * O_ + c1] = o1;
    }
}

// ============================================================================
extern "C" void kernel_launch(void* const* d_in, const int* in_sizes, int n_in,
                              void* d_out, int out_size)
{
    const float* feat = (const float*)d_in[0];   // [F,B,D]
    const float* W1   = (const float*)d_in[1];   // [F,E,D,H]
    const float* b1   = (const float*)d_in[2];   // [F,E,H]
    const float* W2   = (const float*)d_in[3];   // [F,E,H,O]
    const float* b2   = (const float*)d_in[4];   // [F,E,O]
    const float* Wg   = (const float*)d_in[5];   // [F,D,E]
    const float* bg   = (const float*)d_in[6];   // [F,E]
    float* out = (float*)d_out;                  // [B,O]

    gate_kernel<<<dim3(B_ / 256, F_), 256>>>(feat, Wg, bg);
    hidden_kernel<<<dim3(H_ / 128, B_ / 128, FE_), 256>>>(feat, W1, b1);
    out_kernel<<<dim3(O_ / 64, B_ / 128), 128>>>(W2, b2, out);
}

// round 11
// speedup vs baseline: 2.3935x; 2.3926x over previous
#include <cuda_runtime.h>
#include <cuda_bf16.h>
#include <math.h>
#include <stdint.h>

#define F_ 4
#define E_ 8
#define B_ 4096
#define D_ 512
#define H_ 1024
#define O_ 512
#define FE_ (F_*E_)

// GEMM tiling
#define BM 128
#define BN 128
#define BK 64
#define TILE_B 16384                 // 128 rows x 128B (SW128)
#define STAGE_B (4 * TILE_B)         // Ah, Al, Bh, Bl
#define NSTG 2
#define SMEM_TOTAL (NSTG * STAGE_B + 1024)

// ---------------------------------------------------------------------------
// Device scratch (no cudaMalloc allowed)
// ---------------------------------------------------------------------------
__device__ __align__(1024) float g_gate[F_ * B_ * E_];
__device__ __align__(1024) float g_bias[(size_t)B_ * O_];
__device__ __align__(1024) __nv_bfloat16 g_Ah[(size_t)F_ * B_ * D_];
__device__ __align__(1024) __nv_bfloat16 g_Al[(size_t)F_ * B_ * D_];
__device__ __align__(1024) __nv_bfloat16 g_W1h[(size_t)FE_ * H_ * D_];  // W1^T [fe][H][D]
__device__ __align__(1024) __nv_bfloat16 g_W1l[(size_t)FE_ * H_ * D_];
__device__ __align__(1024) __nv_bfloat16 g_W2h[(size_t)FE_ * O_ * H_]; // W2^T [fe][O][H]
__device__ __align__(1024) __nv_bfloat16 g_W2l[(size_t)FE_ * O_ * H_];
__device__ __align__(1024) __nv_bfloat16 g_Hh[(size_t)FE_ * B_ * H_];  // gated hidden hi
__device__ __align__(1024) __nv_bfloat16 g_Hl[(size_t)FE_ * B_ * H_];  // gated hidden lo

// ---------------------------------------------------------------------------
// PTX helpers (all baseline ISA: valid on target sm_103 w/o 'a' features)
// ---------------------------------------------------------------------------
__device__ __forceinline__ uint32_t smem_u32(const void* p) {
    return (uint32_t)__cvta_generic_to_shared(p);
}
__device__ __forceinline__ void cp16(uint32_t dst, const void* src) {
    asm volatile("cp.async.cg.shared.global [%0], [%1], 16;"
                 :: "r"(dst), "l"(__cvta_generic_to_global(src)) : "memory");
}
__device__ __forceinline__ void cp_commit() {
    asm volatile("cp.async.commit_group;" ::: "memory");
}
__device__ __forceinline__ void cp_wait1() {
    asm volatile("cp.async.wait_group 1;" ::: "memory");
}
__device__ __forceinline__ void cp_wait0() {
    asm volatile("cp.async.wait_group 0;" ::: "memory");
}
__device__ __forceinline__ void ldsm4(uint32_t* r, uint32_t addr) {
    asm volatile("ldmatrix.sync.aligned.m8n8.x4.shared.b16 {%0,%1,%2,%3}, [%4];"
                 : "=r"(r[0]), "=r"(r[1]), "=r"(r[2]), "=r"(r[3]) : "r"(addr));
}
__device__ __forceinline__ void mma16816(float* c, const uint32_t* a, const uint32_t* b) {
    asm volatile(
        "mma.sync.aligned.m16n8k16.row.col.f32.bf16.bf16.f32 "
        "{%0,%1,%2,%3}, {%4,%5,%6,%7}, {%8,%9}, {%0,%1,%2,%3};"
        : "+f"(c[0]), "+f"(c[1]), "+f"(c[2]), "+f"(c[3])
        : "r"(a[0]), "r"(a[1]), "r"(a[2]), "r"(a[3]), "r"(b[0]), "r"(b[1]));
}
__device__ __forceinline__ void split2(float a, float b, uint32_t& h, uint32_t& l) {
    __nv_bfloat162 hv = __floats2bfloat162_rn(a, b);
    float2 hf = __bfloat1622float2(hv);
    __nv_bfloat162 lv = __floats2bfloat162_rn(a - hf.x, b - hf.y);
    h = *reinterpret_cast<uint32_t*>(&hv);
    l = *reinterpret_cast<uint32_t*>(&lv);
}

// Load one 4-tile stage (Ah, Al, Bh, Bl), 128 rows x 64 bf16 each, SW128 swizzle.
__device__ __forceinline__ void load_stage(
    uint32_t base,
    const __nv_bfloat16* Ah, const __nv_bfloat16* Al,
    const __nv_bfloat16* Bh, const __nv_bfloat16* Bl,
    int lda, int ldb, int tid)
{
#pragma unroll
    for (int i = 0; i < 4; ++i) {
        const int c   = tid + 256 * i;      // 0..1023 per tile
        const int row = c >> 3;
        const int col = c & 7;
        const uint32_t so = (uint32_t)(row * 128 + ((col * 16) ^ ((row & 7) << 4)));
        const size_t ga = (size_t)row * lda + col * 8;
        const size_t gb = (size_t)row * ldb + col * 8;
        cp16(base + so,              Ah + ga);
        cp16(base + TILE_B + so,     Al + ga);
        cp16(base + 2 * TILE_B + so, Bh + gb);
        cp16(base + 3 * TILE_B + so, Bl + gb);
    }
    cp_commit();
}

// ============================================================================
// gate softmax (pre-scaled by 1/F)
// ============================================================================
__global__ void gate_kernel(const float* __restrict__ feat,
                            const float* __restrict__ Wg,
                            const float* __restrict__ bg)
{
    const int b = blockIdx.x * blockDim.x + threadIdx.x;
    const int f = blockIdx.y;
    const float* x  = feat + ((size_t)f * B_ + b) * D_;
    const float* wg = Wg + (size_t)f * D_ * E_;

    float acc[E_];
#pragma unroll
    for (int e = 0; e < E_; ++e) acc[e] = bg[f * E_ + e];

    for (int d0 = 0; d0 < D_; d0 += 4) {
        float4 xv = *(const float4*)(x + d0);
        float xa[4] = {xv.x, xv.y, xv.z, xv.w};
#pragma unroll
        for (int q = 0; q < 4; ++q) {
            const float4* w = (const float4*)(wg + (size_t)(d0 + q) * E_);
            float4 w0 = w[0], w1 = w[1];
            acc[0] = fmaf(xa[q], w0.x, acc[0]);
            acc[1] = fmaf(xa[q], w0.y, acc[1]);
            acc[2] = fmaf(xa[q], w0.z, acc[2]);
            acc[3] = fmaf(xa[q], w0.w, acc[3]);
            acc[4] = fmaf(xa[q], w1.x, acc[4]);
            acc[5] = fmaf(xa[q], w1.y, acc[5]);
            acc[6] = fmaf(xa[q], w1.z, acc[6]);
            acc[7] = fmaf(xa[q], w1.w, acc[7]);
        }
    }
    float mx = acc[0];
#pragma unroll
    for (int e = 1; e < E_; ++e) mx = fmaxf(mx, acc[e]);
    float s = 0.f;
#pragma unroll
    for (int e = 0; e < E_; ++e) { acc[e] = expf(acc[e] - mx); s += acc[e]; }
    const float inv = 1.f / (s * (float)F_);
#pragma unroll
    for (int e = 0; e < E_; ++e)
        g_gate[((size_t)f * B_ + b) * E_ + e] = acc[e] * inv;
}

// ============================================================================
// bias[b][o] = sum_fe gate(f,b,e)/F * b2[fe][o]
// ============================================================================
__global__ void bias_kernel(const float* __restrict__ b2)
{
    const int o = blockIdx.x * 256 + threadIdx.x;
    const int b = blockIdx.y;
    float acc = 0.f;
#pragma unroll
    for (int fe = 0; fe < FE_; ++fe)
        acc = fmaf(g_gate[((size_t)(fe >> 3) * B_ + b) * E_ + (fe & 7)],
                   b2[(size_t)fe * O_ + o], acc);
    g_bias[(size_t)b * O_ + o] = acc;
}

// ============================================================================
// features fp32 -> (hi, lo) bf16, same layout. 8 elems/thread.
// ============================================================================
__global__ void convA_kernel(const float* __restrict__ src)
{
    const size_t i = ((size_t)blockIdx.x * 256 + threadIdx.x) * 8;
    float4 a = *(const float4*)(src + i);
    float4 b = *(const float4*)(src + i + 4);
    uint4 h, l;
    split2(a.x, a.y, h.x, l.x);
    split2(a.z, a.w, h.y, l.y);
    split2(b.x, b.y, h.z, l.z);
    split2(b.z, b.w, h.w, l.w);
    *(uint4*)(g_Ah + i) = h;
    *(uint4*)(g_Al + i) = l;
}

// ============================================================================
// transpose + split: in[z][R][C] fp32 -> out[z][C][R] bf16 (hi, lo)
// which: 0 = W1 (R=D,C=H), 1 = W2 (R=H,C=O)
// ============================================================================
__global__ void convT_kernel(const float* __restrict__ in, int which)
{
    __nv_bfloat16 *oh, *ol;
    int R, C;
    if (which == 0) { oh = g_W1h; ol = g_W1l; R = D_; C = H_; }
    else            { oh = g_W2h; ol = g_W2l; R = H_; C = O_; }

    __shared__ float t[32][33];
    const size_t zo = (size_t)blockIdx.z * R * C;
    const int x = blockIdx.x * 32 + threadIdx.x;
    const int y = blockIdx.y * 32;
#pragma unroll
    for (int i = 0; i < 32; i += 8)
        t[threadIdx.y + i][threadIdx.x] = in[zo + (size_t)(y + threadIdx.y + i) * C + x];
    __syncthreads();
    const int xo = blockIdx.y * 32 + threadIdx.x;
    const int yo = blockIdx.x * 32;
#pragma unroll
    for (int i = 0; i < 32; i += 8) {
        float v = t[threadIdx.x][threadIdx.y + i];
        __nv_bfloat16 h = __float2bfloat16(v);
        size_t idx = zo + (size_t)(yo + threadIdx.y + i) * R + xo;
        oh[idx] = h;
        ol[idx] = __float2bfloat16(v - __bfloat162float(h));
    }
}

// ---------------------------------------------------------------------------
// Shared mainloop compute: one BK=64 stage of split bf16 HMMA.
// Warp grid 2(m)x4(n), warp tile 64x32. c[4][4][4] accumulators.
// ---------------------------------------------------------------------------
struct LdsmOffsets {
    uint32_t offA[4], xvA[4];   // per mi
    uint32_t offB[2], xvB[2];   // per n-pair
    uint32_t cbA, cbB;
};
__device__ __forceinline__ void make_offsets(LdsmOffsets& o, int wid, int lane) {
    const int wm = wid & 1, wn = wid >> 1;
    o.cbA = ((lane >> 4) & 1) * 16;
    o.cbB = ((lane >> 3) & 1) * 16;
#pragma unroll
    for (int mi = 0; mi < 4; ++mi) {
        int r = wm * 64 + mi * 16 + (lane & 7) + ((lane >> 3) & 1) * 8;
        o.offA[mi] = r * 128;
        o.xvA[mi]  = (r & 7) << 4;
    }
#pragma unroll
    for (int p = 0; p < 2; ++p) {
        int r = wn * 32 + p * 16 + (lane & 7) + ((lane >> 4) & 1) * 8;
        o.offB[p] = r * 128;
        o.xvB[p]  = (r & 7) << 4;
    }
}
__device__ __forceinline__ void compute_stage(uint32_t base, const LdsmOffsets& o,
                                              float c[4][4][4]) {
#pragma unroll
    for (int ks = 0; ks < 4; ++ks) {
        uint32_t ah[4][4], al[4][4], bh[4][2], bl[4][2];
#pragma unroll
        for (int mi = 0; mi < 4; ++mi) {
            uint32_t col = ((uint32_t)(ks * 32) + o.cbA) ^ o.xvA[mi];
            ldsm4(ah[mi], base + o.offA[mi] + col);
            ldsm4(al[mi], base + TILE_B + o.offA[mi] + col);
        }
#pragma unroll
        for (int p = 0; p < 2; ++p) {
            uint32_t col = ((uint32_t)(ks * 32) + o.cbB) ^ o.xvB[p];
            uint32_t t4[4];
            ldsm4(t4, base + 2 * TILE_B + o.offB[p] + col);
            bh[2*p][0] = t4[0]; bh[2*p][1] = t4[1];
            bh[2*p+1][0] = t4[2]; bh[2*p+1][1] = t4[3];
            ldsm4(t4, base + 3 * TILE_B + o.offB[p] + col);
            bl[2*p][0] = t4[0]; bl[2*p][1] = t4[1];
            bl[2*p+1][0] = t4[2]; bl[2*p+1][1] = t4[3];
        }
#pragma unroll
        for (int mi = 0; mi < 4; ++mi)
#pragma unroll
            for (int ni = 0; ni < 4; ++ni)
                mma16816(c[mi][ni], ah[mi], bh[ni]);
#pragma unroll
        for (int mi = 0; mi < 4; ++mi)
#pragma unroll
            for (int ni = 0; ni < 4; ++ni)
                mma16816(c[mi][ni], al[mi], bh[ni]);
#pragma unroll
        for (int mi = 0; mi < 4; ++mi)
#pragma unroll
            for (int ni = 0; ni < 4; ++ni)
                mma16816(c[mi][ni], ah[mi], bl[ni]);
    }
}

// ============================================================================
// GEMM1: H[fe] = gate/F * relu( X[f] @ W1[fe] + b1[fe] ) -> bf16 split pair.
// ============================================================================
__global__ __launch_bounds__(256, 1)
void gemm1_kernel(const float* __restrict__ b1)
{
    extern __shared__ char sm[];
    const uint32_t stg0 = (smem_u32(sm) + 1023u) & ~1023u;
    const int tid = threadIdx.x;
    const int wid = tid >> 5, lane = tid & 31;
    const int fe = blockIdx.z, f = fe >> 3, e = fe & 7;
    const int m0 = blockIdx.y * BM, n0 = blockIdx.x * BN;

    const __nv_bfloat16* Ah = g_Ah + ((size_t)f * B_ + m0) * D_;
    const __nv_bfloat16* Al = g_Al + ((size_t)f * B_ + m0) * D_;
    const __nv_bfloat16* Bh = g_W1h + ((size_t)fe * H_ + n0) * D_;
    const __nv_bfloat16* Bl = g_W1l + ((size_t)fe * H_ + n0) * D_;

    LdsmOffsets off;
    make_offsets(off, wid, lane);

    float c[4][4][4];
#pragma unroll
    for (int i = 0; i < 4; ++i)
#pragma unroll
        for (int j = 0; j < 4; ++j)
#pragma unroll
            for (int q = 0; q < 4; ++q) c[i][j][q] = 0.f;

    load_stage(stg0,           Ah,      Al,      Bh,      Bl,      D_, D_, tid);
    load_stage(stg0 + STAGE_B, Ah + 64, Al + 64, Bh + 64, Bl + 64, D_, D_, tid);

    const int NT = D_ / BK;   // 8
    for (int t = 0; t < NT; ++t) {
        if (t == NT - 1) cp_wait0(); else cp_wait1();
        __syncthreads();
        const uint32_t base = stg0 + (t & 1) * STAGE_B;
        compute_stage(base, off, c);
        __syncthreads();
        if (t + 2 < NT) {
            const int k0 = (t + 2) * BK;
            load_stage(base, Ah + k0, Al + k0, Bh + k0, Bl + k0, D_, D_, tid);
        }
    }

    // Epilogue: +b1, relu, *gate, re-split to bf16 hi/lo
    const int wm = wid & 1, wn = wid >> 1;
    const int rr = lane >> 2, cc = (lane & 3) * 2;
    const float* b1p = b1 + (size_t)fe * H_ + n0 + wn * 32;
#pragma unroll
    for (int mi = 0; mi < 4; ++mi) {
        const int m = m0 + wm * 64 + mi * 16 + rr;
        const float g0 = g_gate[((size_t)f * B_ + m) * E_ + e];
        const float g1 = g_gate[((size_t)f * B_ + m + 8) * E_ + e];
        __nv_bfloat16* ph = g_Hh + ((size_t)fe * B_ + m) * H_ + n0 + wn * 32;
        __nv_bfloat16* pl = g_Hl + ((size_t)fe * B_ + m) * H_ + n0 + wn * 32;
#pragma unroll
        for (int ni = 0; ni < 4; ++ni) {
            const int nc = ni * 8 + cc;
            const float ba = b1p[nc], bb = b1p[nc + 1];
            uint32_t h, l;
            split2(fmaxf(c[mi][ni][0] + ba, 0.f) * g0,
                   fmaxf(c[mi][ni][1] + bb, 0.f) * g0, h, l);
            *(uint32_t*)(ph + nc) = h;
            *(uint32_t*)(pl + nc) = l;
            split2(fmaxf(c[mi][ni][2] + ba, 0.f) * g1,
                   fmaxf(c[mi][ni][3] + bb, 0.f) * g1, h, l);
            *(uint32_t*)(ph + 8 * H_ + nc) = h;
            *(uint32_t*)(pl + 8 * H_ + nc) = l;
        }
    }
}

// ============================================================================
// GEMM2: out = sum_fe H[fe] @ W2^T[fe] + g_bias.  K = 32*1024 = 32768.
// ============================================================================
__global__ __launch_bounds__(256, 1)
void gemm2_kernel(float* __restrict__ out)
{
    extern __shared__ char sm[];
    const uint32_t stg0 = (smem_u32(sm) + 1023u) & ~1023u;
    const int tid = threadIdx.x;
    const int wid = tid >> 5, lane = tid & 31;
    const int m0 = blockIdx.y * BM, n0 = blockIdx.x * BN;

    LdsmOffsets off;
    make_offsets(off, wid, lane);

    float c[4][4][4];
#pragma unroll
    for (int i = 0; i < 4; ++i)
#pragma unroll
        for (int j = 0; j < 4; ++j)
#pragma unroll
            for (int q = 0; q < 4; ++q) c[i][j][q] = 0.f;

    auto ld = [&](int s, uint32_t buf) {
        const int feS = s >> 4;
        const int k0 = (s & 15) << 6;
        load_stage(buf,
                   g_Hh  + ((size_t)feS * B_ + m0) * H_ + k0,
                   g_Hl  + ((size_t)feS * B_ + m0) * H_ + k0,
                   g_W2h + ((size_t)feS * O_ + n0) * H_ + k0,
                   g_W2l + ((size_t)feS * O_ + n0) * H_ + k0,
                   H_, H_, tid);
    };

    ld(0, stg0);
    ld(1, stg0 + STAGE_B);

    const int NT = FE_ * (H_ / BK);   // 512
    for (int t = 0; t < NT; ++t) {
        if (t == NT - 1) cp_wait0(); else cp_wait1();
        __syncthreads();
        const uint32_t base = stg0 + (t & 1) * STAGE_B;
        compute_stage(base, off, c);
        __syncthreads();
        if (t + 2 < NT) ld(t + 2, base);
    }

    // Epilogue: + precomputed bias, fp32 store
    const int wm = wid & 1, wn = wid >> 1;
    const int rr = lane >> 2, cc = (lane & 3) * 2;
#pragma unroll
    for (int mi = 0; mi < 4; ++mi) {
        const int m = m0 + wm * 64 + mi * 16 + rr;
        float* op = out + (size_t)m * O_ + n0 + wn * 32;
        const float* bp = g_bias + (size_t)m * O_ + n0 + wn * 32;
#pragma unroll
        for (int ni = 0; ni < 4; ++ni) {
            const int nc = ni * 8 + cc;
            float2 o0 = {c[mi][ni][0] + bp[nc], c[mi][ni][1] + bp[nc + 1]};
            *(float2*)(op + nc) = o0;
            float2 o1 = {c[mi][ni][2] + bp[8 * O_ + nc], c[mi][ni][3] + bp[8 * O_ + nc + 1]};
            *(float2*)(op + 8 * O_ + nc) = o1;
        }
    }
}

// ============================================================================
extern "C" void kernel_launch(void* const* d_in, const int* in_sizes, int n_in,
                              void* d_out, int out_size)
{
    const float* feat = (const float*)d_in[0];
    const float* W1   = (const float*)d_in[1];
    const float* b1   = (const float*)d_in[2];
    const float* W2   = (const float*)d_in[3];
    const float* b2   = (const float*)d_in[4];
    const float* Wg   = (const float*)d_in[5];
    const float* bg   = (const float*)d_in[6];
    float* out = (float*)d_out;

    cudaFuncSetAttribute(gemm1_kernel, cudaFuncAttributeMaxDynamicSharedMemorySize, SMEM_TOTAL);
    cudaFuncSetAttribute(gemm2_kernel, cudaFuncAttributeMaxDynamicSharedMemorySize, SMEM_TOTAL);

    gate_kernel<<<dim3(B_ / 256, F_), 256>>>(feat, Wg, bg);
    bias_kernel<<<dim3(O_ / 256, B_), 256>>>(b2);
    convA_kernel<<<(F_ * B_ * D_) / (256 * 8), 256>>>(feat);
    convT_kernel<<<dim3(H_ / 32, D_ / 32, FE_), dim3(32, 8)>>>(W1, 0);
    convT_kernel<<<dim3(O_ / 32, H_ / 32, FE_), dim3(32, 8)>>>(W2, 1);
    gemm1_kernel<<<dim3(H_ / BN, B_ / BM, FE_), 256, SMEM_TOTAL>>>(b1);
    gemm2_kernel<<<dim3(O_ / BN, B_ / BM), 256, SMEM_TOTAL>>>(out);
}

// round 12
// speedup vs baseline: 2.4339x; 1.0169x over previous
#include <cuda_runtime.h>
#include <cuda_bf16.h>
#include <math.h>
#include <stdint.h>

#define F_ 4
#define E_ 8
#define B_ 4096
#define D_ 512
#define H_ 1024
#define O_ 512
#define FE_ (F_*E_)

// GEMM tiling: BM=128, BN=128, BK=32. hi/lo interleaved in 128B rows.
#define BM 128
#define BN 128
#define BK 32
#define BUF_B 16384                  // one interleaved buffer: 128 rows x 128B
#define STAGE_B (2 * BUF_B)          // A-buf + B-buf
#define NSTG 3
#define SMEM_TOTAL (NSTG * STAGE_B + 1024)
#define KSPLIT 4

// ---------------------------------------------------------------------------
// Device scratch (no cudaMalloc allowed)
// ---------------------------------------------------------------------------
__device__ __align__(1024) float g_gate[F_ * B_ * E_];
__device__ __align__(1024) float g_bias[(size_t)B_ * O_];
__device__ __align__(1024) float g_part[(size_t)KSPLIT * B_ * O_];
__device__ __align__(1024) __nv_bfloat16 g_Ah[(size_t)F_ * B_ * D_];
__device__ __align__(1024) __nv_bfloat16 g_Al[(size_t)F_ * B_ * D_];
__device__ __align__(1024) __nv_bfloat16 g_W1h[(size_t)FE_ * H_ * D_];  // W1^T [fe][H][D]
__device__ __align__(1024) __nv_bfloat16 g_W1l[(size_t)FE_ * H_ * D_];
__device__ __align__(1024) __nv_bfloat16 g_W2h[(size_t)FE_ * O_ * H_]; // W2^T [fe][O][H]
__device__ __align__(1024) __nv_bfloat16 g_W2l[(size_t)FE_ * O_ * H_];
__device__ __align__(1024) __nv_bfloat16 g_Hh[(size_t)FE_ * B_ * H_];  // gated hidden hi
__device__ __align__(1024) __nv_bfloat16 g_Hl[(size_t)FE_ * B_ * H_];  // gated hidden lo

// ---------------------------------------------------------------------------
// PTX helpers (baseline ISA only — valid on plain sm_103 target)
// ---------------------------------------------------------------------------
__device__ __forceinline__ uint32_t smem_u32(const void* p) {
    return (uint32_t)__cvta_generic_to_shared(p);
}
__device__ __forceinline__ void cp16(uint32_t dst, const void* src) {
    asm volatile("cp.async.cg.shared.global [%0], [%1], 16;"
                 :: "r"(dst), "l"(__cvta_generic_to_global(src)) : "memory");
}
__device__ __forceinline__ void cp_commit() {
    asm volatile("cp.async.commit_group;" ::: "memory");
}
__device__ __forceinline__ void cp_wait2() {
    asm volatile("cp.async.wait_group 2;" ::: "memory");
}
__device__ __forceinline__ void cp_wait1() {
    asm volatile("cp.async.wait_group 1;" ::: "memory");
}
__device__ __forceinline__ void cp_wait0() {
    asm volatile("cp.async.wait_group 0;" ::: "memory");
}
__device__ __forceinline__ void ldsm4(uint32_t* r, uint32_t addr) {
    asm volatile("ldmatrix.sync.aligned.m8n8.x4.shared.b16 {%0,%1,%2,%3}, [%4];"
                 : "=r"(r[0]), "=r"(r[1]), "=r"(r[2]), "=r"(r[3]) : "r"(addr));
}
__device__ __forceinline__ void mma16816(float* c, const uint32_t* a, const uint32_t* b) {
    asm volatile(
        "mma.sync.aligned.m16n8k16.row.col.f32.bf16.bf16.f32 "
        "{%0,%1,%2,%3}, {%4,%5,%6,%7}, {%8,%9}, {%0,%1,%2,%3};"
        : "+f"(c[0]), "+f"(c[1]), "+f"(c[2]), "+f"(c[3])
        : "r"(a[0]), "r"(a[1]), "r"(a[2]), "r"(a[3]), "r"(b[0]), "r"(b[1]));
}
__device__ __forceinline__ void split2(float a, float b, uint32_t& h, uint32_t& l) {
    __nv_bfloat162 hv = __floats2bfloat162_rn(a, b);
    float2 hf = __bfloat1622float2(hv);
    __nv_bfloat162 lv = __floats2bfloat162_rn(a - hf.x, b - hf.y);
    h = *reinterpret_cast<uint32_t*>(&hv);
    l = *reinterpret_cast<uint32_t*>(&lv);
}

// Load one stage: A-buf (Ah|Al interleaved) + B-buf (Bh|Bl interleaved).
// Each buffer: 128 rows x 128B SW128. cols 0..3 = hi (32 bf16), 4..7 = lo.
__device__ __forceinline__ void load_stage(
    uint32_t base,
    const __nv_bfloat16* Ah, const __nv_bfloat16* Al,
    const __nv_bfloat16* Bh, const __nv_bfloat16* Bl,
    int lda, int ldb, int tid)
{
#pragma unroll
    for (int i = 0; i < 4; ++i) {
        const int c   = tid + 256 * i;      // 0..1023
        const int row = c >> 3;
        const int col = c & 7;
        const uint32_t so = (uint32_t)(row * 128 + ((col * 16) ^ ((row & 7) << 4)));
        const int ko = (col & 3) * 8;
        const __nv_bfloat16* sa = (col < 4) ? (Ah + (size_t)row * lda + ko)
                                            : (Al + (size_t)row * lda + ko);
        const __nv_bfloat16* sb = (col < 4) ? (Bh + (size_t)row * ldb + ko)
                                            : (Bl + (size_t)row * ldb + ko);
        cp16(base + so,         sa);
        cp16(base + BUF_B + so, sb);
    }
    cp_commit();
}

// ============================================================================
// gate softmax (pre-scaled by 1/F)
// ============================================================================
__global__ void gate_kernel(const float* __restrict__ feat,
                            const float* __restrict__ Wg,
                            const float* __restrict__ bg)
{
    const int b = blockIdx.x * blockDim.x + threadIdx.x;
    const int f = blockIdx.y;
    const float* x  = feat + ((size_t)f * B_ + b) * D_;
    const float* wg = Wg + (size_t)f * D_ * E_;

    float acc[E_];
#pragma unroll
    for (int e = 0; e < E_; ++e) acc[e] = bg[f * E_ + e];

    for (int d0 = 0; d0 < D_; d0 += 4) {
        float4 xv = *(const float4*)(x + d0);
        float xa[4] = {xv.x, xv.y, xv.z, xv.w};
#pragma unroll
        for (int q = 0; q < 4; ++q) {
            const float4* w = (const float4*)(wg + (size_t)(d0 + q) * E_);
            float4 w0 = w[0], w1 = w[1];
            acc[0] = fmaf(xa[q], w0.x, acc[0]);
            acc[1] = fmaf(xa[q], w0.y, acc[1]);
            acc[2] = fmaf(xa[q], w0.z, acc[2]);
            acc[3] = fmaf(xa[q], w0.w, acc[3]);
            acc[4] = fmaf(xa[q], w1.x, acc[4]);
            acc[5] = fmaf(xa[q], w1.y, acc[5]);
            acc[6] = fmaf(xa[q], w1.z, acc[6]);
            acc[7] = fmaf(xa[q], w1.w, acc[7]);
        }
    }
    float mx = acc[0];
#pragma unroll
    for (int e = 1; e < E_; ++e) mx = fmaxf(mx, acc[e]);
    float s = 0.f;
#pragma unroll
    for (int e = 0; e < E_; ++e) { acc[e] = expf(acc[e] - mx); s += acc[e]; }
    const float inv = 1.f / (s * (float)F_);
#pragma unroll
    for (int e = 0; e < E_; ++e)
        g_gate[((size_t)f * B_ + b) * E_ + e] = acc[e] * inv;
}

// ============================================================================
// bias[b][o] = sum_fe gate(f,b,e)/F * b2[fe][o]
// ============================================================================
__global__ void bias_kernel(const float* __restrict__ b2)
{
    const int o = blockIdx.x * 256 + threadIdx.x;
    const int b = blockIdx.y;
    float acc = 0.f;
#pragma unroll
    for (int fe = 0; fe < FE_; ++fe)
        acc = fmaf(g_gate[((size_t)(fe >> 3) * B_ + b) * E_ + (fe & 7)],
                   b2[(size_t)fe * O_ + o], acc);
    g_bias[(size_t)b * O_ + o] = acc;
}

// ============================================================================
// features fp32 -> (hi, lo) bf16, same layout. 8 elems/thread.
// ============================================================================
__global__ void convA_kernel(const float* __restrict__ src)
{
    const size_t i = ((size_t)blockIdx.x * 256 + threadIdx.x) * 8;
    float4 a = *(const float4*)(src + i);
    float4 b = *(const float4*)(src + i + 4);
    uint4 h, l;
    split2(a.x, a.y, h.x, l.x);
    split2(a.z, a.w, h.y, l.y);
    split2(b.x, b.y, h.z, l.z);
    split2(b.z, b.w, h.w, l.w);
    *(uint4*)(g_Ah + i) = h;
    *(uint4*)(g_Al + i) = l;
}

// ============================================================================
// transpose + split: in[z][R][C] fp32 -> out[z][C][R] bf16 (hi, lo)
// ============================================================================
__global__ void convT_kernel(const float* __restrict__ in, int which)
{
    __nv_bfloat16 *oh, *ol;
    int R, C;
    if (which == 0) { oh = g_W1h; ol = g_W1l; R = D_; C = H_; }
    else            { oh = g_W2h; ol = g_W2l; R = H_; C = O_; }

    __shared__ float t[32][33];
    const size_t zo = (size_t)blockIdx.z * R * C;
    const int x = blockIdx.x * 32 + threadIdx.x;
    const int y = blockIdx.y * 32;
#pragma unroll
    for (int i = 0; i < 32; i += 8)
        t[threadIdx.y + i][threadIdx.x] = in[zo + (size_t)(y + threadIdx.y + i) * C + x];
    __syncthreads();
    const int xo = blockIdx.y * 32 + threadIdx.x;
    const int yo = blockIdx.x * 32;
#pragma unroll
    for (int i = 0; i < 32; i += 8) {
        float v = t[threadIdx.x][threadIdx.y + i];
        __nv_bfloat16 h = __float2bfloat16(v);
        size_t idx = zo + (size_t)(yo + threadIdx.y + i) * R + xo;
        oh[idx] = h;
        ol[idx] = __float2bfloat16(v - __bfloat162float(h));
    }
}

// ---------------------------------------------------------------------------
// Mainloop compute: one BK=32 stage. Warps 2(m)x4(n), warp tile 64x32.
// hi at col bytes [0,64), lo at [64,128) within each buffer row.
// ---------------------------------------------------------------------------
struct LdsmOffsets {
    uint32_t offA[4], xvA[4];
    uint32_t offB[2], xvB[2];
    uint32_t cbA, cbB;
};
__device__ __forceinline__ void make_offsets(LdsmOffsets& o, int wid, int lane) {
    const int wm = wid & 1, wn = wid >> 1;
    o.cbA = ((lane >> 4) & 1) * 16;
    o.cbB = ((lane >> 3) & 1) * 16;
#pragma unroll
    for (int mi = 0; mi < 4; ++mi) {
        int r = wm * 64 + mi * 16 + (lane & 7) + ((lane >> 3) & 1) * 8;
        o.offA[mi] = r * 128;
        o.xvA[mi]  = (r & 7) << 4;
    }
#pragma unroll
    for (int p = 0; p < 2; ++p) {
        int r = wn * 32 + p * 16 + (lane & 7) + ((lane >> 4) & 1) * 8;
        o.offB[p] = r * 128;
        o.xvB[p]  = (r & 7) << 4;
    }
}
__device__ __forceinline__ void compute_stage(uint32_t abase, uint32_t bbase,
                                              const LdsmOffsets& o, float c[4][4][4]) {
#pragma unroll
    for (int ks = 0; ks < 2; ++ks) {
        uint32_t bh[4][2], bl[4][2];
#pragma unroll
        for (int p = 0; p < 2; ++p) {
            const uint32_t colh = ((uint32_t)(ks * 32) + o.cbB) ^ o.xvB[p];
            const uint32_t coll = (64u + (uint32_t)(ks * 32) + o.cbB) ^ o.xvB[p];
            uint32_t t4[4];
            ldsm4(t4, bbase + o.offB[p] + colh);
            bh[2*p][0] = t4[0]; bh[2*p][1] = t4[1];
            bh[2*p+1][0] = t4[2]; bh[2*p+1][1] = t4[3];
            ldsm4(t4, bbase + o.offB[p] + coll);
            bl[2*p][0] = t4[0]; bl[2*p][1] = t4[1];
            bl[2*p+1][0] = t4[2]; bl[2*p+1][1] = t4[3];
        }
#pragma unroll
        for (int mi = 0; mi < 4; ++mi) {
            uint32_t ah[4], al[4];
            ldsm4(ah, abase + o.offA[mi] + ((((uint32_t)(ks * 32)) + o.cbA) ^ o.xvA[mi]));
            ldsm4(al, abase + o.offA[mi] + ((64u + (uint32_t)(ks * 32) + o.cbA) ^ o.xvA[mi]));
#pragma unroll
            for (int ni = 0; ni < 4; ++ni) mma16816(c[mi][ni], ah, bh[ni]);
#pragma unroll
            for (int ni = 0; ni < 4; ++ni) mma16816(c[mi][ni], al, bh[ni]);
#pragma unroll
            for (int ni = 0; ni < 4; ++ni) mma16816(c[mi][ni], ah, bl[ni]);
        }
    }
}

// ============================================================================
// GEMM1: H[fe] = gate/F * relu( X[f] @ W1[fe] + b1[fe] ) -> bf16 split pair.
// ============================================================================
__global__ __launch_bounds__(256, 2)
void gemm1_kernel(const float* __restrict__ b1)
{
    extern __shared__ char sm[];
    const uint32_t stg0 = (smem_u32(sm) + 1023u) & ~1023u;
    const int tid = threadIdx.x;
    const int wid = tid >> 5, lane = tid & 31;
    const int fe = blockIdx.z, f = fe >> 3, e = fe & 7;
    const int m0 = blockIdx.y * BM, n0 = blockIdx.x * BN;

    const __nv_bfloat16* Ah = g_Ah + ((size_t)f * B_ + m0) * D_;
    const __nv_bfloat16* Al = g_Al + ((size_t)f * B_ + m0) * D_;
    const __nv_bfloat16* Bh = g_W1h + ((size_t)fe * H_ + n0) * D_;
    const __nv_bfloat16* Bl = g_W1l + ((size_t)fe * H_ + n0) * D_;

    LdsmOffsets off;
    make_offsets(off, wid, lane);

    float c[4][4][4];
#pragma unroll
    for (int i = 0; i < 4; ++i)
#pragma unroll
        for (int j = 0; j < 4; ++j)
#pragma unroll
            for (int q = 0; q < 4; ++q) c[i][j][q] = 0.f;

    const int NT = D_ / BK;   // 16
    load_stage(stg0,               Ah,          Al,          Bh,          Bl,          D_, D_, tid);
    load_stage(stg0 + STAGE_B,     Ah + BK,     Al + BK,     Bh + BK,     Bl + BK,     D_, D_, tid);
    load_stage(stg0 + 2 * STAGE_B, Ah + 2 * BK, Al + 2 * BK, Bh + 2 * BK, Bl + 2 * BK, D_, D_, tid);

    for (int t = 0; t < NT; ++t) {
        if (t < NT - 2) cp_wait2();
        else if (t == NT - 2) cp_wait1();
        else cp_wait0();
        __syncthreads();
        const uint32_t base = stg0 + (t % NSTG) * STAGE_B;
        compute_stage(base, base + BUF_B, off, c);
        __syncthreads();
        if (t + 3 < NT) {
            const int k0 = (t + 3) * BK;
            load_stage(base, Ah + k0, Al + k0, Bh + k0, Bl + k0, D_, D_, tid);
        }
    }

    // Epilogue: +b1, relu, *gate, re-split to bf16 hi/lo
    const int wm = wid & 1, wn = wid >> 1;
    const int rr = lane >> 2, cc = (lane & 3) * 2;
    const float* b1p = b1 + (size_t)fe * H_ + n0 + wn * 32;
#pragma unroll
    for (int mi = 0; mi < 4; ++mi) {
        const int m = m0 + wm * 64 + mi * 16 + rr;
        const float g0 = g_gate[((size_t)f * B_ + m) * E_ + e];
        const float g1 = g_gate[((size_t)f * B_ + m + 8) * E_ + e];
        __nv_bfloat16* ph = g_Hh + ((size_t)fe * B_ + m) * H_ + n0 + wn * 32;
        __nv_bfloat16* pl = g_Hl + ((size_t)fe * B_ + m) * H_ + n0 + wn * 32;
#pragma unroll
        for (int ni = 0; ni < 4; ++ni) {
            const int nc = ni * 8 + cc;
            const float ba = b1p[nc], bb = b1p[nc + 1];
            uint32_t h, l;
            split2(fmaxf(c[mi][ni][0] + ba, 0.f) * g0,
                   fmaxf(c[mi][ni][1] + bb, 0.f) * g0, h, l);
            *(uint32_t*)(ph + nc) = h;
            *(uint32_t*)(pl + nc) = l;
            split2(fmaxf(c[mi][ni][2] + ba, 0.f) * g1,
                   fmaxf(c[mi][ni][3] + bb, 0.f) * g1, h, l);
            *(uint32_t*)(ph + 8 * H_ + nc) = h;
            *(uint32_t*)(pl + 8 * H_ + nc) = l;
        }
    }
}

// ============================================================================
// GEMM2 (split-K): part[s] = sum_{fe in split s} H[fe] @ W2^T[fe].
// ============================================================================
__global__ __launch_bounds__(256, 2)
void gemm2_kernel()
{
    extern __shared__ char sm[];
    const uint32_t stg0 = (smem_u32(sm) + 1023u) & ~1023u;
    const int tid = threadIdx.x;
    const int wid = tid >> 5, lane = tid & 31;
    const int m0 = blockIdx.y * BM, n0 = blockIdx.x * BN;
    const int split = blockIdx.z;
    const int fe0 = split * (FE_ / KSPLIT);

    LdsmOffsets off;
    make_offsets(off, wid, lane);

    float c[4][4][4];
#pragma unroll
    for (int i = 0; i < 4; ++i)
#pragma unroll
        for (int j = 0; j < 4; ++j)
#pragma unroll
            for (int q = 0; q < 4; ++q) c[i][j][q] = 0.f;

    auto ld = [&](int s, uint32_t buf) {
        const int fe = fe0 + (s >> 5);          // 32 stages per fe (H/BK)
        const int k0 = (s & 31) * BK;
        load_stage(buf,
                   g_Hh  + ((size_t)fe * B_ + m0) * H_ + k0,
                   g_Hl  + ((size_t)fe * B_ + m0) * H_ + k0,
                   g_W2h + ((size_t)fe * O_ + n0) * H_ + k0,
                   g_W2l + ((size_t)fe * O_ + n0) * H_ + k0,
                   H_, H_, tid);
    };

    ld(0, stg0);
    ld(1, stg0 + STAGE_B);
    ld(2, stg0 + 2 * STAGE_B);

    const int NT = (FE_ / KSPLIT) * (H_ / BK);   // 256
    for (int t = 0; t < NT; ++t) {
        if (t < NT - 2) cp_wait2();
        else if (t == NT - 2) cp_wait1();
        else cp_wait0();
        __syncthreads();
        const uint32_t base = stg0 + (t % NSTG) * STAGE_B;
        compute_stage(base, base + BUF_B, off, c);
        __syncthreads();
        if (t + 3 < NT) ld(t + 3, base);
    }

    // Epilogue: store fp32 partials
    const int wm = wid & 1, wn = wid >> 1;
    const int rr = lane >> 2, cc = (lane & 3) * 2;
    float* part = g_part + (size_t)split * B_ * O_;
#pragma unroll
    for (int mi = 0; mi < 4; ++mi) {
        const int m = m0 + wm * 64 + mi * 16 + rr;
        float* op = part + (size_t)m * O_ + n0 + wn * 32;
#pragma unroll
        for (int ni = 0; ni < 4; ++ni) {
            const int nc = ni * 8 + cc;
            *(float2*)(op + nc) = make_float2(c[mi][ni][0], c[mi][ni][1]);
            *(float2*)(op + 8 * O_ + nc) = make_float2(c[mi][ni][2], c[mi][ni][3]);
        }
    }
}

// ============================================================================
// reduce: out = bias + sum_s part[s]
// ============================================================================
__global__ void reduce_kernel(float* __restrict__ out)
{
    const size_t i = ((size_t)blockIdx.x * 256 + threadIdx.x) * 4;
    float4 a = *(const float4*)(g_bias + i);
#pragma unroll
    for (int s = 0; s < KSPLIT; ++s) {
        float4 p = *(const float4*)(g_part + (size_t)s * B_ * O_ + i);
        a.x += p.x; a.y += p.y; a.z += p.z; a.w += p.w;
    }
    *(float4*)(out + i) = a;
}

// ============================================================================
extern "C" void kernel_launch(void* const* d_in, const int* in_sizes, int n_in,
                              void* d_out, int out_size)
{
    const float* feat = (const float*)d_in[0];
    const float* W1   = (const float*)d_in[1];
    const float* b1   = (const float*)d_in[2];
    const float* W2   = (const float*)d_in[3];
    const float* b2   = (const float*)d_in[4];
    const float* Wg   = (const float*)d_in[5];
    const float* bg   = (const float*)d_in[6];
    float* out = (float*)d_out;

    cudaFuncSetAttribute(gemm1_kernel, cudaFuncAttributeMaxDynamicSharedMemorySize, SMEM_TOTAL);
    cudaFuncSetAttribute(gemm2_kernel, cudaFuncAttributeMaxDynamicSharedMemorySize, SMEM_TOTAL);

    gate_kernel<<<dim3(B_ / 256, F_), 256>>>(feat, Wg, bg);
    bias_kernel<<<dim3(O_ / 256, B_), 256>>>(b2);
    convA_kernel<<<(F_ * B_ * D_) / (256 * 8), 256>>>(feat);
    convT_kernel<<<dim3(H_ / 32, D_ / 32, FE_), dim3(32, 8)>>>(W1, 0);
    convT_kernel<<<dim3(O_ / 32, H_ / 32, FE_), dim3(32, 8)>>>(W2, 1);
    gemm1_kernel<<<dim3(H_ / BN, B_ / BM, FE_), 256, SMEM_TOTAL>>>(b1);
    gemm2_kernel<<<dim3(O_ / BN, B_ / BM, KSPLIT), 256, SMEM_TOTAL>>>();
    reduce_kernel<<<(B_ * O_) / (256 * 4), 256>>>(out);
}

// round 13
// speedup vs baseline: 3.8271x; 1.5724x over previous
#include <cuda_runtime.h>
#include <cuda_fp16.h>
#include <math.h>
#include <stdint.h>

#define F_ 4
#define E_ 8
#define B_ 4096
#define D_ 512
#define H_ 1024
#define O_ 512
#define FE_ (F_*E_)

// GEMM tiling: BM=128, BN=128, BK=64.
// Stage = Ah tile (16KB) + Al tile (16KB) + B tile (16KB), 128B SW128 rows.
#define BM 128
#define BN 128
#define BK 64
#define TILE_B 16384
#define STAGE_B (3 * TILE_B)
#define NSTG 2
#define SMEM_TOTAL (NSTG * STAGE_B + 1024)
#define KSPLIT 8

// ---------------------------------------------------------------------------
// Device scratch (no cudaMalloc allowed)
// ---------------------------------------------------------------------------
__device__ __align__(1024) float g_gate[F_ * B_ * E_];
__device__ __align__(1024) float g_bias[(size_t)B_ * O_];
__device__ __align__(1024) float g_part[(size_t)KSPLIT * B_ * O_];
__device__ __align__(1024) __half g_Ah[(size_t)F_ * B_ * D_];       // features hi
__device__ __align__(1024) __half g_Al[(size_t)F_ * B_ * D_];       // features lo
__device__ __align__(1024) __half g_W1[(size_t)FE_ * H_ * D_];      // W1^T [fe][H][D], fp16
__device__ __align__(1024) __half g_W2[(size_t)FE_ * O_ * H_];      // W2^T [fe][O][H], fp16
__device__ __align__(1024) __half g_Hh[(size_t)FE_ * B_ * H_];      // gated hidden hi
__device__ __align__(1024) __half g_Hl[(size_t)FE_ * B_ * H_];      // gated hidden lo

// ---------------------------------------------------------------------------
// PTX helpers (baseline ISA only — valid on plain sm_103 target)
// ---------------------------------------------------------------------------
__device__ __forceinline__ uint32_t smem_u32(const void* p) {
    return (uint32_t)__cvta_generic_to_shared(p);
}
__device__ __forceinline__ void cp16(uint32_t dst, const void* src) {
    asm volatile("cp.async.cg.shared.global [%0], [%1], 16;"
                 :: "r"(dst), "l"(__cvta_generic_to_global(src)) : "memory");
}
__device__ __forceinline__ void cp_commit() {
    asm volatile("cp.async.commit_group;" ::: "memory");
}
__device__ __forceinline__ void cp_wait1() {
    asm volatile("cp.async.wait_group 1;" ::: "memory");
}
__device__ __forceinline__ void cp_wait0() {
    asm volatile("cp.async.wait_group 0;" ::: "memory");
}
__device__ __forceinline__ void ldsm4(uint32_t* r, uint32_t addr) {
    asm volatile("ldmatrix.sync.aligned.m8n8.x4.shared.b16 {%0,%1,%2,%3}, [%4];"
                 : "=r"(r[0]), "=r"(r[1]), "=r"(r[2]), "=r"(r[3]) : "r"(addr));
}
__device__ __forceinline__ void mma16816(float* c, const uint32_t* a, const uint32_t* b) {
    asm volatile(
        "mma.sync.aligned.m16n8k16.row.col.f32.f16.f16.f32 "
        "{%0,%1,%2,%3}, {%4,%5,%6,%7}, {%8,%9}, {%0,%1,%2,%3};"
        : "+f"(c[0]), "+f"(c[1]), "+f"(c[2]), "+f"(c[3])
        : "r"(a[0]), "r"(a[1]), "r"(a[2]), "r"(a[3]), "r"(b[0]), "r"(b[1]));
}
// split two fp32 into fp16 hi pair + fp16 lo pair (packed u32 each)
__device__ __forceinline__ void split2h(float a, float b, uint32_t& h, uint32_t& l) {
    __half2 hv = __floats2half2_rn(a, b);
    float2 hf = __half22float2(hv);
    __half2 lv = __floats2half2_rn(a - hf.x, b - hf.y);
    h = *reinterpret_cast<uint32_t*>(&hv);
    l = *reinterpret_cast<uint32_t*>(&lv);
}

// Load one stage: Ah, Al, B tiles, each 128 rows x 64 fp16 (128B rows, SW128).
__device__ __forceinline__ void load_stage(
    uint32_t base,
    const __half* Ah, const __half* Al, const __half* Bt,
    int lda, int ldb, int tid)
{
#pragma unroll
    for (int i = 0; i < 4; ++i) {
        const int c   = tid + 256 * i;      // 0..1023 per tile
        const int row = c >> 3;
        const int col = c & 7;
        const uint32_t so = (uint32_t)(row * 128 + ((col * 16) ^ ((row & 7) << 4)));
        const size_t ga = (size_t)row * lda + col * 8;
        const size_t gb = (size_t)row * ldb + col * 8;
        cp16(base + so,              Ah + ga);
        cp16(base + TILE_B + so,     Al + ga);
        cp16(base + 2 * TILE_B + so, Bt + gb);
    }
    cp_commit();
}

// ============================================================================
// gate softmax (pre-scaled by 1/F)
// ============================================================================
__global__ void gate_kernel(const float* __restrict__ feat,
                            const float* __restrict__ Wg,
                            const float* __restrict__ bg)
{
    const int b = blockIdx.x * blockDim.x + threadIdx.x;
    const int f = blockIdx.y;
    const float* x  = feat + ((size_t)f * B_ + b) * D_;
    const float* wg = Wg + (size_t)f * D_ * E_;

    float acc[E_];
#pragma unroll
    for (int e = 0; e < E_; ++e) acc[e] = bg[f * E_ + e];

    for (int d0 = 0; d0 < D_; d0 += 4) {
        float4 xv = *(const float4*)(x + d0);
        float xa[4] = {xv.x, xv.y, xv.z, xv.w};
#pragma unroll
        for (int q = 0; q < 4; ++q) {
            const float4* w = (const float4*)(wg + (size_t)(d0 + q) * E_);
            float4 w0 = w[0], w1 = w[1];
            acc[0] = fmaf(xa[q], w0.x, acc[0]);
            acc[1] = fmaf(xa[q], w0.y, acc[1]);
            acc[2] = fmaf(xa[q], w0.z, acc[2]);
            acc[3] = fmaf(xa[q], w0.w, acc[3]);
            acc[4] = fmaf(xa[q], w1.x, acc[4]);
            acc[5] = fmaf(xa[q], w1.y, acc[5]);
            acc[6] = fmaf(xa[q], w1.z, acc[6]);
            acc[7] = fmaf(xa[q], w1.w, acc[7]);
        }
    }
    float mx = acc[0];
#pragma unroll
    for (int e = 1; e < E_; ++e) mx = fmaxf(mx, acc[e]);
    float s = 0.f;
#pragma unroll
    for (int e = 0; e < E_; ++e) { acc[e] = expf(acc[e] - mx); s += acc[e]; }
    const float inv = 1.f / (s * (float)F_);
#pragma unroll
    for (int e = 0; e < E_; ++e)
        g_gate[((size_t)f * B_ + b) * E_ + e] = acc[e] * inv;
}

// ============================================================================
// bias[b][o] = sum_fe gate(f,b,e)/F * b2[fe][o]
// ============================================================================
__global__ void bias_kernel(const float* __restrict__ b2)
{
    const int o = blockIdx.x * 256 + threadIdx.x;
    const int b = blockIdx.y;
    float acc = 0.f;
#pragma unroll
    for (int fe = 0; fe < FE_; ++fe)
        acc = fmaf(g_gate[((size_t)(fe >> 3) * B_ + b) * E_ + (fe & 7)],
                   b2[(size_t)fe * O_ + o], acc);
    g_bias[(size_t)b * O_ + o] = acc;
}

// ============================================================================
// features fp32 -> (hi, lo) fp16, same layout. 8 elems/thread.
// ============================================================================
__global__ void convA_kernel(const float* __restrict__ src)
{
    const size_t i = ((size_t)blockIdx.x * 256 + threadIdx.x) * 8;
    float4 a = *(const float4*)(src + i);
    float4 b = *(const float4*)(src + i + 4);
    uint4 h, l;
    split2h(a.x, a.y, h.x, l.x);
    split2h(a.z, a.w, h.y, l.y);
    split2h(b.x, b.y, h.z, l.z);
    split2h(b.z, b.w, h.w, l.w);
    *(uint4*)(g_Ah + i) = h;
    *(uint4*)(g_Al + i) = l;
}

// ============================================================================
// transpose: in[z][R][C] fp32 -> out[z][C][R] fp16 (single, rounded)
// which: 0 = W1 (R=D,C=H), 1 = W2 (R=H,C=O)
// ============================================================================
__global__ void convT_kernel(const float* __restrict__ in, int which)
{
    __half* oh;
    int R, C;
    if (which == 0) { oh = g_W1; R = D_; C = H_; }
    else            { oh = g_W2; R = H_; C = O_; }

    __shared__ float t[32][33];
    const size_t zo = (size_t)blockIdx.z * R * C;
    const int x = blockIdx.x * 32 + threadIdx.x;
    const int y = blockIdx.y * 32;
#pragma unroll
    for (int i = 0; i < 32; i += 8)
        t[threadIdx.y + i][threadIdx.x] = in[zo + (size_t)(y + threadIdx.y + i) * C + x];
    __syncthreads();
    const int xo = blockIdx.y * 32 + threadIdx.x;
    const int yo = blockIdx.x * 32;
#pragma unroll
    for (int i = 0; i < 32; i += 8) {
        float v = t[threadIdx.x][threadIdx.y + i];
        oh[zo + (size_t)(yo + threadIdx.y + i) * R + xo] = __float2half_rn(v);
    }
}

// ---------------------------------------------------------------------------
// Mainloop compute: one BK=64 stage, 2-term split (Ah·B + Al·B).
// Warps 2(m)x4(n), warp tile 64x32.
// ---------------------------------------------------------------------------
struct LdsmOffsets {
    uint32_t offA[4], xvA[4];
    uint32_t offB[2], xvB[2];
    uint32_t cbA, cbB;
};
__device__ __forceinline__ void make_offsets(LdsmOffsets& o, int wid, int lane) {
    const int wm = wid & 1, wn = wid >> 1;
    o.cbA = ((lane >> 4) & 1) * 16;
    o.cbB = ((lane >> 3) & 1) * 16;
#pragma unroll
    for (int mi = 0; mi < 4; ++mi) {
        int r = wm * 64 + mi * 16 + (lane & 7) + ((lane >> 3) & 1) * 8;
        o.offA[mi] = r * 128;
        o.xvA[mi]  = (r & 7) << 4;
    }
#pragma unroll
    for (int p = 0; p < 2; ++p) {
        int r = wn * 32 + p * 16 + (lane & 7) + ((lane >> 4) & 1) * 8;
        o.offB[p] = r * 128;
        o.xvB[p]  = (r & 7) << 4;
    }
}
__device__ __forceinline__ void compute_stage(uint32_t base, const LdsmOffsets& o,
                                              float c[4][4][4]) {
#pragma unroll
    for (int ks = 0; ks < 4; ++ks) {
        uint32_t bh[4][2];
#pragma unroll
        for (int p = 0; p < 2; ++p) {
            const uint32_t col = ((uint32_t)(ks * 32) + o.cbB) ^ o.xvB[p];
            uint32_t t4[4];
            ldsm4(t4, base + 2 * TILE_B + o.offB[p] + col);
            bh[2*p][0] = t4[0]; bh[2*p][1] = t4[1];
            bh[2*p+1][0] = t4[2]; bh[2*p+1][1] = t4[3];
        }
#pragma unroll
        for (int mi = 0; mi < 4; ++mi) {
            uint32_t ah[4], al[4];
            const uint32_t col = (((uint32_t)(ks * 32)) + o.cbA) ^ o.xvA[mi];
            ldsm4(ah, base + o.offA[mi] + col);
            ldsm4(al, base + TILE_B + o.offA[mi] + col);
#pragma unroll
            for (int ni = 0; ni < 4; ++ni) mma16816(c[mi][ni], ah, bh[ni]);
#pragma unroll
            for (int ni = 0; ni < 4; ++ni) mma16816(c[mi][ni], al, bh[ni]);
        }
    }
}

// ============================================================================
// GEMM1: H[fe] = gate/F * relu( X[f] @ W1[fe] + b1[fe] ) -> fp16 split pair.
// ============================================================================
__global__ __launch_bounds__(256, 2)
void gemm1_kernel(const float* __restrict__ b1)
{
    extern __shared__ char sm[];
    const uint32_t stg0 = (smem_u32(sm) + 1023u) & ~1023u;
    const int tid = threadIdx.x;
    const int wid = tid >> 5, lane = tid & 31;
    const int fe = blockIdx.z, f = fe >> 3, e = fe & 7;
    const int m0 = blockIdx.y * BM, n0 = blockIdx.x * BN;

    const __half* Ah = g_Ah + ((size_t)f * B_ + m0) * D_;
    const __half* Al = g_Al + ((size_t)f * B_ + m0) * D_;
    const __half* Bt = g_W1 + ((size_t)fe * H_ + n0) * D_;

    LdsmOffsets off;
    make_offsets(off, wid, lane);

    float c[4][4][4];
#pragma unroll
    for (int i = 0; i < 4; ++i)
#pragma unroll
        for (int j = 0; j < 4; ++j)
#pragma unroll
            for (int q = 0; q < 4; ++q) c[i][j][q] = 0.f;

    load_stage(stg0,           Ah,      Al,      Bt,      D_, D_, tid);
    load_stage(stg0 + STAGE_B, Ah + BK, Al + BK, Bt + BK, D_, D_, tid);

    const int NT = D_ / BK;   // 8
    for (int t = 0; t < NT; ++t) {
        if (t == NT - 1) cp_wait0(); else cp_wait1();
        __syncthreads();
        const uint32_t base = stg0 + (t & 1) * STAGE_B;
        compute_stage(base, off, c);
        __syncthreads();
        if (t + 2 < NT) {
            const int k0 = (t + 2) * BK;
            load_stage(base, Ah + k0, Al + k0, Bt + k0, D_, D_, tid);
        }
    }

    // Epilogue: +b1, relu, *gate, split to fp16 hi/lo
    const int wm = wid & 1, wn = wid >> 1;
    const int rr = lane >> 2, cc = (lane & 3) * 2;
    const float* b1p = b1 + (size_t)fe * H_ + n0 + wn * 32;
#pragma unroll
    for (int mi = 0; mi < 4; ++mi) {
        const int m = m0 + wm * 64 + mi * 16 + rr;
        const float g0 = g_gate[((size_t)f * B_ + m) * E_ + e];
        const float g1 = g_gate[((size_t)f * B_ + m + 8) * E_ + e];
        __half* ph = g_Hh + ((size_t)fe * B_ + m) * H_ + n0 + wn * 32;
        __half* pl = g_Hl + ((size_t)fe * B_ + m) * H_ + n0 + wn * 32;
#pragma unroll
        for (int ni = 0; ni < 4; ++ni) {
            const int nc = ni * 8 + cc;
            const float ba = b1p[nc], bb = b1p[nc + 1];
            uint32_t h, l;
            split2h(fmaxf(c[mi][ni][0] + ba, 0.f) * g0,
                    fmaxf(c[mi][ni][1] + bb, 0.f) * g0, h, l);
            *(uint32_t*)(ph + nc) = h;
            *(uint32_t*)(pl + nc) = l;
            split2h(fmaxf(c[mi][ni][2] + ba, 0.f) * g1,
                    fmaxf(c[mi][ni][3] + bb, 0.f) * g1, h, l);
            *(uint32_t*)(ph + 8 * H_ + nc) = h;
            *(uint32_t*)(pl + 8 * H_ + nc) = l;
        }
    }
}

// ============================================================================
// GEMM2 (split-K): part[s] = sum_{fe in split s} H[fe] @ W2^T[fe].
// ============================================================================
__global__ __launch_bounds__(256, 2)
void gemm2_kernel()
{
    extern __shared__ char sm[];
    const uint32_t stg0 = (smem_u32(sm) + 1023u) & ~1023u;
    const int tid = threadIdx.x;
    const int wid = tid >> 5, lane = tid & 31;
    const int m0 = blockIdx.y * BM, n0 = blockIdx.x * BN;
    const int split = blockIdx.z;
    const int fe0 = split * (FE_ / KSPLIT);

    LdsmOffsets off;
    make_offsets(off, wid, lane);

    float c[4][4][4];
#pragma unroll
    for (int i = 0; i < 4; ++i)
#pragma unroll
        for (int j = 0; j < 4; ++j)
#pragma unroll
            for (int q = 0; q < 4; ++q) c[i][j][q] = 0.f;

    auto ld = [&](int s, uint32_t buf) {
        const int fe = fe0 + (s >> 4);          // 16 stages per fe (H/BK)
        const int k0 = (s & 15) * BK;
        load_stage(buf,
                   g_Hh + ((size_t)fe * B_ + m0) * H_ + k0,
                   g_Hl + ((size_t)fe * B_ + m0) * H_ + k0,
                   g_W2 + ((size_t)fe * O_ + n0) * H_ + k0,
                   H_, H_, tid);
    };

    ld(0, stg0);
    ld(1, stg0 + STAGE_B);

    const int NT = (FE_ / KSPLIT) * (H_ / BK);   // 64
    for (int t = 0; t < NT; ++t) {
        if (t == NT - 1) cp_wait0(); else cp_wait1();
        __syncthreads();
        const uint32_t base = stg0 + (t & 1) * STAGE_B;
        compute_stage(base, off, c);
        __syncthreads();
        if (t + 2 < NT) ld(t + 2, base);
    }

    // Epilogue: store fp32 partials
    const int wm = wid & 1, wn = wid >> 1;
    const int rr = lane >> 2, cc = (lane & 3) * 2;
    float* part = g_part + (size_t)split * B_ * O_;
#pragma unroll
    for (int mi = 0; mi < 4; ++mi) {
        const int m = m0 + wm * 64 + mi * 16 + rr;
        float* op = part + (size_t)m * O_ + n0 + wn * 32;
#pragma unroll
        for (int ni = 0; ni < 4; ++ni) {
            const int nc = ni * 8 + cc;
            *(float2*)(op + nc) = make_float2(c[mi][ni][0], c[mi][ni][1]);
            *(float2*)(op + 8 * O_ + nc) = make_float2(c[mi][ni][2], c[mi][ni][3]);
        }
    }
}

// ============================================================================
// reduce: out = bias + sum_s part[s]
// ============================================================================
__global__ void reduce_kernel(float* __restrict__ out)
{
    const size_t i = ((size_t)blockIdx.x * 256 + threadIdx.x) * 4;
    float4 a = *(const float4*)(g_bias + i);
#pragma unroll
    for (int s = 0; s < KSPLIT; ++s) {
        float4 p = *(const float4*)(g_part + (size_t)s * B_ * O_ + i);
        a.x += p.x; a.y += p.y; a.z += p.z; a.w += p.w;
    }
    *(float4*)(out + i) = a;
}

// ============================================================================
extern "C" void kernel_launch(void* const* d_in, const int* in_sizes, int n_in,
                              void* d_out, int out_size)
{
    const float* feat = (const float*)d_in[0];
    const float* W1   = (const float*)d_in[1];
    const float* b1   = (const float*)d_in[2];
    const float* W2   = (const float*)d_in[3];
    const float* b2   = (const float*)d_in[4];
    const float* Wg   = (const float*)d_in[5];
    const float* bg   = (const float*)d_in[6];
    float* out = (float*)d_out;

    cudaFuncSetAttribute(gemm1_kernel, cudaFuncAttributeMaxDynamicSharedMemorySize, SMEM_TOTAL);
    cudaFuncSetAttribute(gemm2_kernel, cudaFuncAttributeMaxDynamicSharedMemorySize, SMEM_TOTAL);

    gate_kernel<<<dim3(B_ / 256, F_), 256>>>(feat, Wg, bg);
    bias_kernel<<<dim3(O_ / 256, B_), 256>>>(b2);
    convA_kernel<<<(F_ * B_ * D_) / (256 * 8), 256>>>(feat);
    convT_kernel<<<dim3(H_ / 32, D_ / 32, FE_), dim3(32, 8)>>>(W1, 0);
    convT_kernel<<<dim3(O_ / 32, H_ / 32, FE_), dim3(32, 8)>>>(W2, 1);
    gemm1_kernel<<<dim3(H_ / BN, B_ / BM, FE_), 256, SMEM_TOTAL>>>(b1);
    gemm2_kernel<<<dim3(O_ / BN, B_ / BM, KSPLIT), 256, SMEM_TOTAL>>>();
    reduce_kernel<<<(B_ * O_) / (256 * 4), 256>>>(out);
}

// round 14
// speedup vs baseline: 6.6029x; 1.7253x over previous
#include <cuda_runtime.h>
#include <cuda_fp16.h>
#include <math.h>
#include <stdint.h>

#define F_ 4
#define E_ 8
#define B_ 4096
#define D_ 512
#define H_ 1024
#define O_ 512
#define FE_ (F_*E_)

// GEMM tiling: BM=128, BN=128, BK=64. Stage = A tile + B tile (16KB each).
#define BM 128
#define BN 128
#define BK 64
#define TILE_B 16384
#define STAGE_B (2 * TILE_B)
#define NSTG 3
#define SMEM_TOTAL (NSTG * STAGE_B + 1024)
#define KSPLIT 4

// ---------------------------------------------------------------------------
// Device scratch (no cudaMalloc allowed)
// ---------------------------------------------------------------------------
__device__ __align__(1024) float g_gate[F_ * B_ * E_];
__device__ __align__(1024) float g_bias[(size_t)B_ * O_];
__device__ __align__(1024) float g_part[(size_t)KSPLIT * B_ * O_];
__device__ __align__(1024) __half g_A[(size_t)F_ * B_ * D_];        // features fp16
__device__ __align__(1024) __half g_W1[(size_t)FE_ * H_ * D_];      // W1^T [fe][H][D]
__device__ __align__(1024) __half g_W2[(size_t)FE_ * O_ * H_];      // W2^T [fe][O][H]
__device__ __align__(1024) __half g_H[(size_t)FE_ * B_ * H_];       // gated hidden fp16

// ---------------------------------------------------------------------------
// PTX helpers (baseline ISA only — valid on plain sm_103 target)
// ---------------------------------------------------------------------------
__device__ __forceinline__ uint32_t smem_u32(const void* p) {
    return (uint32_t)__cvta_generic_to_shared(p);
}
__device__ __forceinline__ void cp16(uint32_t dst, const void* src) {
    asm volatile("cp.async.cg.shared.global [%0], [%1], 16;"
                 :: "r"(dst), "l"(__cvta_generic_to_global(src)) : "memory");
}
__device__ __forceinline__ void cp_commit() {
    asm volatile("cp.async.commit_group;" ::: "memory");
}
__device__ __forceinline__ void cp_wait2() {
    asm volatile("cp.async.wait_group 2;" ::: "memory");
}
__device__ __forceinline__ void cp_wait1() {
    asm volatile("cp.async.wait_group 1;" ::: "memory");
}
__device__ __forceinline__ void cp_wait0() {
    asm volatile("cp.async.wait_group 0;" ::: "memory");
}
__device__ __forceinline__ void ldsm4(uint32_t* r, uint32_t addr) {
    asm volatile("ldmatrix.sync.aligned.m8n8.x4.shared.b16 {%0,%1,%2,%3}, [%4];"
                 : "=r"(r[0]), "=r"(r[1]), "=r"(r[2]), "=r"(r[3]) : "r"(addr));
}
__device__ __forceinline__ void mma16816(float* c, const uint32_t* a, const uint32_t* b) {
    asm volatile(
        "mma.sync.aligned.m16n8k16.row.col.f32.f16.f16.f32 "
        "{%0,%1,%2,%3}, {%4,%5,%6,%7}, {%8,%9}, {%0,%1,%2,%3};"
        : "+f"(c[0]), "+f"(c[1]), "+f"(c[2]), "+f"(c[3])
        : "r"(a[0]), "r"(a[1]), "r"(a[2]), "r"(a[3]), "r"(b[0]), "r"(b[1]));
}

// Load one stage: A tile + B tile, each 128 rows x 64 fp16 (128B rows, SW128).
__device__ __forceinline__ void load_stage(
    uint32_t base, const __half* A, const __half* Bt, int lda, int ldb, int tid)
{
#pragma unroll
    for (int i = 0; i < 4; ++i) {
        const int c   = tid + 256 * i;      // 0..1023 per tile
        const int row = c >> 3;
        const int col = c & 7;
        const uint32_t so = (uint32_t)(row * 128 + ((col * 16) ^ ((row & 7) << 4)));
        cp16(base + so,          A  + (size_t)row * lda + col * 8);
        cp16(base + TILE_B + so, Bt + (size_t)row * ldb + col * 8);
    }
    cp_commit();
}

// ============================================================================
// gate softmax (pre-scaled by 1/F). Warp-per-row, Wg staged in smem.
// Block: 256 threads = 8 warps = 8 batch rows. Grid: (B/8, F).
// ============================================================================
__global__ __launch_bounds__(256)
void gate_kernel(const float* __restrict__ feat,
                 const float* __restrict__ Wg,
                 const float* __restrict__ bg)
{
    __shared__ float wg_s[D_ * 9];   // padded rows of 9 (conflict-free LDS)
    const int tid = threadIdx.x;
    const int f = blockIdx.y;

    // Stage Wg[f] (512x8 f32) into smem
    const float* wg = Wg + (size_t)f * D_ * E_;
#pragma unroll
    for (int i = 0; i < 16; ++i) {
        const int idx = tid + 256 * i;           // 0..4095
        wg_s[(idx >> 3) * 9 + (idx & 7)] = wg[idx];
    }
    __syncthreads();

    const int wid = tid >> 5, lane = tid & 31;
    const int b = blockIdx.x * 8 + wid;
    const float* x = feat + ((size_t)f * B_ + b) * D_;

    float acc[E_] = {0.f, 0.f, 0.f, 0.f, 0.f, 0.f, 0.f, 0.f};
#pragma unroll
    for (int k = 0; k < D_ / 32; ++k) {
        const int d = lane + 32 * k;
        const float xv = x[d];
        const float* w = wg_s + d * 9;
#pragma unroll
        for (int e = 0; e < E_; ++e) acc[e] = fmaf(xv, w[e], acc[e]);
    }
#pragma unroll
    for (int e = 0; e < E_; ++e) {
#pragma unroll
        for (int off = 16; off > 0; off >>= 1)
            acc[e] += __shfl_down_sync(0xFFFFFFFFu, acc[e], off);
    }
    if (lane == 0) {
#pragma unroll
        for (int e = 0; e < E_; ++e) acc[e] += bg[f * E_ + e];
        float mx = acc[0];
#pragma unroll
        for (int e = 1; e < E_; ++e) mx = fmaxf(mx, acc[e]);
        float s = 0.f;
#pragma unroll
        for (int e = 0; e < E_; ++e) { acc[e] = expf(acc[e] - mx); s += acc[e]; }
        const float inv = 1.f / (s * (float)F_);
#pragma unroll
        for (int e = 0; e < E_; ++e)
            g_gate[((size_t)f * B_ + b) * E_ + e] = acc[e] * inv;
    }
}

// ============================================================================
// bias[b][o] = sum_fe gate(f,b,e)/F * b2[fe][o]
// ============================================================================
__global__ void bias_kernel(const float* __restrict__ b2)
{
    const int o = blockIdx.x * 256 + threadIdx.x;
    const int b = blockIdx.y;
    float acc = 0.f;
#pragma unroll
    for (int fe = 0; fe < FE_; ++fe)
        acc = fmaf(g_gate[((size_t)(fe >> 3) * B_ + b) * E_ + (fe & 7)],
                   b2[(size_t)fe * O_ + o], acc);
    g_bias[(size_t)b * O_ + o] = acc;
}

// ============================================================================
// features fp32 -> fp16. 8 elems/thread.
// ============================================================================
__global__ void convA_kernel(const float* __restrict__ src)
{
    const size_t i = ((size_t)blockIdx.x * 256 + threadIdx.x) * 8;
    float4 a = *(const float4*)(src + i);
    float4 b = *(const float4*)(src + i + 4);
    uint4 h;
    __half2 h0 = __floats2half2_rn(a.x, a.y);
    __half2 h1 = __floats2half2_rn(a.z, a.w);
    __half2 h2 = __floats2half2_rn(b.x, b.y);
    __half2 h3 = __floats2half2_rn(b.z, b.w);
    h.x = *reinterpret_cast<uint32_t*>(&h0);
    h.y = *reinterpret_cast<uint32_t*>(&h1);
    h.z = *reinterpret_cast<uint32_t*>(&h2);
    h.w = *reinterpret_cast<uint32_t*>(&h3);
    *(uint4*)(g_A + i) = h;
}

// ============================================================================
// transpose: in[z][R][C] fp32 -> out[z][C][R] fp16
// which: 0 = W1 (R=D,C=H), 1 = W2 (R=H,C=O)
// ============================================================================
__global__ void convT_kernel(const float* __restrict__ in, int which)
{
    __half* oh;
    int R, C;
    if (which == 0) { oh = g_W1; R = D_; C = H_; }
    else            { oh = g_W2; R = H_; C = O_; }

    __shared__ float t[32][33];
    const size_t zo = (size_t)blockIdx.z * R * C;
    const int x = blockIdx.x * 32 + threadIdx.x;
    const int y = blockIdx.y * 32;
#pragma unroll
    for (int i = 0; i < 32; i += 8)
        t[threadIdx.y + i][threadIdx.x] = in[zo + (size_t)(y + threadIdx.y + i) * C + x];
    __syncthreads();
    const int xo = blockIdx.y * 32 + threadIdx.x;
    const int yo = blockIdx.x * 32;
#pragma unroll
    for (int i = 0; i < 32; i += 8) {
        float v = t[threadIdx.x][threadIdx.y + i];
        oh[zo + (size_t)(yo + threadIdx.y + i) * R + xo] = __float2half_rn(v);
    }
}

// ---------------------------------------------------------------------------
// Mainloop compute: one BK=64 stage, single fp16 term.
// Warps 2(m)x4(n), warp tile 64x32. 64 MMAs/stage.
// ---------------------------------------------------------------------------
struct LdsmOffsets {
    uint32_t offA[4], xvA[4];
    uint32_t offB[2], xvB[2];
    uint32_t cbA, cbB;
};
__device__ __forceinline__ void make_offsets(LdsmOffsets& o, int wid, int lane) {
    const int wm = wid & 1, wn = wid >> 1;
    o.cbA = ((lane >> 4) & 1) * 16;
    o.cbB = ((lane >> 3) & 1) * 16;
#pragma unroll
    for (int mi = 0; mi < 4; ++mi) {
        int r = wm * 64 + mi * 16 + (lane & 7) + ((lane >> 3) & 1) * 8;
        o.offA[mi] = r * 128;
        o.xvA[mi]  = (r & 7) << 4;
    }
#pragma unroll
    for (int p = 0; p < 2; ++p) {
        int r = wn * 32 + p * 16 + (lane & 7) + ((lane >> 4) & 1) * 8;
        o.offB[p] = r * 128;
        o.xvB[p]  = (r & 7) << 4;
    }
}
__device__ __forceinline__ void compute_stage(uint32_t base, const LdsmOffsets& o,
                                              float c[4][4][4]) {
#pragma unroll
    for (int ks = 0; ks < 4; ++ks) {
        uint32_t bh[4][2];
#pragma unroll
        for (int p = 0; p < 2; ++p) {
            const uint32_t col = ((uint32_t)(ks * 32) + o.cbB) ^ o.xvB[p];
            uint32_t t4[4];
            ldsm4(t4, base + TILE_B + o.offB[p] + col);
            bh[2*p][0] = t4[0]; bh[2*p][1] = t4[1];
            bh[2*p+1][0] = t4[2]; bh[2*p+1][1] = t4[3];
        }
#pragma unroll
        for (int mi = 0; mi < 4; ++mi) {
            uint32_t ah[4];
            const uint32_t col = (((uint32_t)(ks * 32)) + o.cbA) ^ o.xvA[mi];
            ldsm4(ah, base + o.offA[mi] + col);
#pragma unroll
            for (int ni = 0; ni < 4; ++ni) mma16816(c[mi][ni], ah, bh[ni]);
        }
    }
}

// ============================================================================
// GEMM1: H[fe] = fp16( gate/F * relu( X[f] @ W1[fe] + b1[fe] ) )
// ============================================================================
__global__ __launch_bounds__(256, 2)
void gemm1_kernel(const float* __restrict__ b1)
{
    extern __shared__ char sm[];
    const uint32_t stg0 = (smem_u32(sm) + 1023u) & ~1023u;
    const int tid = threadIdx.x;
    const int wid = tid >> 5, lane = tid & 31;
    const int fe = blockIdx.z, f = fe >> 3, e = fe & 7;
    const int m0 = blockIdx.y * BM, n0 = blockIdx.x * BN;

    const __half* A  = g_A  + ((size_t)f * B_ + m0) * D_;
    const __half* Bt = g_W1 + ((size_t)fe * H_ + n0) * D_;

    LdsmOffsets off;
    make_offsets(off, wid, lane);

    float c[4][4][4];
#pragma unroll
    for (int i = 0; i < 4; ++i)
#pragma unroll
        for (int j = 0; j < 4; ++j)
#pragma unroll
            for (int q = 0; q < 4; ++q) c[i][j][q] = 0.f;

    const int NT = D_ / BK;   // 8
    load_stage(stg0,               A,          Bt,          D_, D_, tid);
    load_stage(stg0 + STAGE_B,     A + BK,     Bt + BK,     D_, D_, tid);
    load_stage(stg0 + 2 * STAGE_B, A + 2 * BK, Bt + 2 * BK, D_, D_, tid);

    for (int t = 0; t < NT; ++t) {
        if (t < NT - 2) cp_wait2();
        else if (t == NT - 2) cp_wait1();
        else cp_wait0();
        __syncthreads();
        const uint32_t base = stg0 + (t % NSTG) * STAGE_B;
        compute_stage(base, off, c);
        __syncthreads();
        if (t + 3 < NT) {
            const int k0 = (t + 3) * BK;
            load_stage(base, A + k0, Bt + k0, D_, D_, tid);
        }
    }

    // Epilogue: +b1, relu, *gate, fp16 store
    const int wm = wid & 1, wn = wid >> 1;
    const int rr = lane >> 2, cc = (lane & 3) * 2;
    const float* b1p = b1 + (size_t)fe * H_ + n0 + wn * 32;
#pragma unroll
    for (int mi = 0; mi < 4; ++mi) {
        const int m = m0 + wm * 64 + mi * 16 + rr;
        const float g0 = g_gate[((size_t)f * B_ + m) * E_ + e];
        const float g1 = g_gate[((size_t)f * B_ + m + 8) * E_ + e];
        __half* ph = g_H + ((size_t)fe * B_ + m) * H_ + n0 + wn * 32;
#pragma unroll
        for (int ni = 0; ni < 4; ++ni) {
            const int nc = ni * 8 + cc;
            const float ba = b1p[nc], bb = b1p[nc + 1];
            __half2 v0 = __floats2half2_rn(fmaxf(c[mi][ni][0] + ba, 0.f) * g0,
                                           fmaxf(c[mi][ni][1] + bb, 0.f) * g0);
            *(uint32_t*)(ph + nc) = *reinterpret_cast<uint32_t*>(&v0);
            __half2 v1 = __floats2half2_rn(fmaxf(c[mi][ni][2] + ba, 0.f) * g1,
                                           fmaxf(c[mi][ni][3] + bb, 0.f) * g1);
            *(uint32_t*)(ph + 8 * H_ + nc) = *reinterpret_cast<uint32_t*>(&v1);
        }
    }
}

// ============================================================================
// GEMM2 (split-K): part[s] = sum_{fe in split s} H[fe] @ W2^T[fe].
// ============================================================================
__global__ __launch_bounds__(256, 2)
void gemm2_kernel()
{
    extern __shared__ char sm[];
    const uint32_t stg0 = (smem_u32(sm) + 1023u) & ~1023u;
    const int tid = threadIdx.x;
    const int wid = tid >> 5, lane = tid & 31;
    const int m0 = blockIdx.y * BM, n0 = blockIdx.x * BN;
    const int split = blockIdx.z;
    const int fe0 = split * (FE_ / KSPLIT);

    LdsmOffsets off;
    make_offsets(off, wid, lane);

    float c[4][4][4];
#pragma unroll
    for (int i = 0; i < 4; ++i)
#pragma unroll
        for (int j = 0; j < 4; ++j)
#pragma unroll
            for (int q = 0; q < 4; ++q) c[i][j][q] = 0.f;

    auto ld = [&](int s, uint32_t buf) {
        const int fe = fe0 + (s >> 4);          // 16 stages per fe (H/BK)
        const int k0 = (s & 15) * BK;
        load_stage(buf,
                   g_H  + ((size_t)fe * B_ + m0) * H_ + k0,
                   g_W2 + ((size_t)fe * O_ + n0) * H_ + k0,
                   H_, H_, tid);
    };

    ld(0, stg0);
    ld(1, stg0 + STAGE_B);
    ld(2, stg0 + 2 * STAGE_B);

    const int NT = (FE_ / KSPLIT) * (H_ / BK);   // 128
    for (int t = 0; t < NT; ++t) {
        if (t < NT - 2) cp_wait2();
        else if (t == NT - 2) cp_wait1();
        else cp_wait0();
        __syncthreads();
        const uint32_t base = stg0 + (t % NSTG) * STAGE_B;
        compute_stage(base, off, c);
        __syncthreads();
        if (t + 3 < NT) ld(t + 3, base);
    }

    // Epilogue: store fp32 partials
    const int wm = wid & 1, wn = wid >> 1;
    const int rr = lane >> 2, cc = (lane & 3) * 2;
    float* part = g_part + (size_t)split * B_ * O_;
#pragma unroll
    for (int mi = 0; mi < 4; ++mi) {
        const int m = m0 + wm * 64 + mi * 16 + rr;
        float* op = part + (size_t)m * O_ + n0 + wn * 32;
#pragma unroll
        for (int ni = 0; ni < 4; ++ni) {
            const int nc = ni * 8 + cc;
            *(float2*)(op + nc) = make_float2(c[mi][ni][0], c[mi][ni][1]);
            *(float2*)(op + 8 * O_ + nc) = make_float2(c[mi][ni][2], c[mi][ni][3]);
        }
    }
}

// ============================================================================
// reduce: out = bias + sum_s part[s]
// ============================================================================
__global__ void reduce_kernel(float* __restrict__ out)
{
    const size_t i = ((size_t)blockIdx.x * 256 + threadIdx.x) * 4;
    float4 a = *(const float4*)(g_bias + i);
#pragma unroll
    for (int s = 0; s < KSPLIT; ++s) {
        float4 p = *(const float4*)(g_part + (size_t)s * B_ * O_ + i);
        a.x += p.x; a.y += p.y; a.z += p.z; a.w += p.w;
    }
    *(float4*)(out + i) = a;
}

// ============================================================================
extern "C" void kernel_launch(void* const* d_in, const int* in_sizes, int n_in,
                              void* d_out, int out_size)
{
    const float* feat = (const float*)d_in[0];
    const float* W1   = (const float*)d_in[1];
    const float* b1   = (const float*)d_in[2];
    const float* W2   = (const float*)d_in[3];
    const float* b2   = (const float*)d_in[4];
    const float* Wg   = (const float*)d_in[5];
    const float* bg   = (const float*)d_in[6];
    float* out = (float*)d_out;

    cudaFuncSetAttribute(gemm1_kernel, cudaFuncAttributeMaxDynamicSharedMemorySize, SMEM_TOTAL);
    cudaFuncSetAttribute(gemm2_kernel, cudaFuncAttributeMaxDynamicSharedMemorySize, SMEM_TOTAL);

    gate_kernel<<<dim3(B_ / 8, F_), 256>>>(feat, Wg, bg);
    bias_kernel<<<dim3(O_ / 256, B_), 256>>>(b2);
    convA_kernel<<<(F_ * B_ * D_) / (256 * 8), 256>>>(feat);
    convT_kernel<<<dim3(H_ / 32, D_ / 32, FE_), dim3(32, 8)>>>(W1, 0);
    convT_kernel<<<dim3(O_ / 32, H_ / 32, FE_), dim3(32, 8)>>>(W2, 1);
    gemm1_kernel<<<dim3(H_ / BN, B_ / BM, FE_), 256, SMEM_TOTAL>>>(b1);
    gemm2_kernel<<<dim3(O_ / BN, B_ / BM, KSPLIT), 256, SMEM_TOTAL>>>();
    reduce_kernel<<<(B_ * O_) / (256 * 4), 256>>>(out);
}